// round 3
// baseline (speedup 1.0000x reference)
#include <cuda_runtime.h>
#include <math.h>

// ---------------- problem constants ----------------
#define BATCH 32
#define IH 120
#define IW 640
#define C1 256
#define KH1 30
#define KW1 160
#define OH1 91
#define OW1 121
#define C2 256
#define OH2 9
#define OW2 12
#define KTOT2 25600          // 256*10*10
#define NCAP 3456
#define NCLS 5
#define FD 16
#define JD 80                // NCLS*FD
#define NREL 25

// ---------------- device scratch (no runtime allocation allowed) ----------------
__device__ float g_conv1[BATCH * C1 * OH1 * OW1];   // 90,202,112 floats (~361 MB)
__device__ float g_prim[BATCH * C2 * OH2 * OW2];    // 884,736
__device__ float g_up[BATCH * NCAP * JD];           // 8,847,360
__device__ float g_bb[BATCH * NCAP * NCLS];
__device__ float g_cc[BATCH * NCAP * NCLS];
__device__ float g_v[BATCH * NCLS * FD];

// ---------------- packed f32x2 helpers (sm_103a FFMA2) ----------------
__device__ __forceinline__ void fma2(unsigned long long& d, unsigned long long a,
                                     unsigned long long b) {
    asm("fma.rn.f32x2 %0, %1, %2, %0;" : "+l"(d) : "l"(a), "l"(b));
}
__device__ __forceinline__ unsigned long long pack2(float x) {
    unsigned long long r;
    asm("mov.b64 %0, {%1, %1};" : "=l"(r) : "f"(x));
    return r;
}
__device__ __forceinline__ void unpack2(unsigned long long v, float& lo, float& hi) {
    asm("mov.b64 {%0, %1}, %2;" : "=f"(lo), "=f"(hi) : "l"(v));
}

// =====================================================================
// Kernel 1: conv1 + bias + relu.   out (B,256,91,121)
// Block: 256 threads (16x16). Tile: 128 channels x 128 ow (121 used),
// fixed (b, oh). For each kh, ONE 640-float input row feeds the whole
// kw x ow tile. Inner math in packed f32x2 (channel pairs).
// =====================================================================
__global__ __launch_bounds__(256, 2)
void conv1_kernel(const float* __restrict__ in, const float* __restrict__ w,
                  const float* __restrict__ bias, float* __restrict__ out) {
    __shared__ float s_in[672];        // 640 + pad (ow up to 127 reads junk, masked)
    __shared__ float s_w[8][128];      // [kk][channel]

    const int tx = threadIdx.x & 15;   // ow group
    const int ty = threadIdx.x >> 4;   // channel group (8 consecutive channels)
    const int ct = blockIdx.x * 128;   // channel tile base
    const int oh = blockIdx.y;
    const int b  = blockIdx.z;

    unsigned long long acc[4][8];      // [channel pair m][ow j]
#pragma unroll
    for (int m = 0; m < 4; ++m)
#pragma unroll
        for (int j = 0; j < 8; ++j) acc[m][j] = 0ULL;

    const int wc = threadIdx.x >> 1;          // weight-load channel 0..127
    const int wk = (threadIdx.x & 1) * 4;     // weight-load kw sub-offset

    for (int kh = 0; kh < KH1; ++kh) {
        __syncthreads();
        // load input row (b, oh+kh)
        {
            const float4* src = (const float4*)(in + ((size_t)b * IH + oh + kh) * IW);
            for (int idx = threadIdx.x; idx < IW / 4; idx += 256)
                ((float4*)s_in)[idx] = src[idx];
        }
        for (int kw0 = 0; kw0 < KW1; kw0 += 8) {
            if (kw0) __syncthreads();
            // load weights s_w[kk][c] for kk=kw0..kw0+7, c=0..127
            {
                float4 wv = *(const float4*)&w[(size_t)(ct + wc) * (KH1 * KW1) +
                                               kh * KW1 + kw0 + wk];
                s_w[wk + 0][wc] = wv.x;
                s_w[wk + 1][wc] = wv.y;
                s_w[wk + 2][wc] = wv.z;
                s_w[wk + 3][wc] = wv.w;
            }
            __syncthreads();
#pragma unroll
            for (int kk = 0; kk < 8; ++kk) {
                // 8 channels = 4 f32x2 pairs
                ulonglong2 w01 = *(const ulonglong2*)&s_w[kk][ty * 8];
                ulonglong2 w23 = *(const ulonglong2*)&s_w[kk][ty * 8 + 4];
                const int bi = 4 * tx + kw0 + kk;
#pragma unroll
                for (int j = 0; j < 8; ++j) {
                    unsigned long long xp = pack2(s_in[bi + 64 * j]);
                    fma2(acc[0][j], w01.x, xp);
                    fma2(acc[1][j], w01.y, xp);
                    fma2(acc[2][j], w23.x, xp);
                    fma2(acc[3][j], w23.y, xp);
                }
            }
        }
    }

    // epilogue: bias + relu + store
#pragma unroll
    for (int m = 0; m < 4; ++m) {
        const int c0 = ct + ty * 8 + 2 * m;
        const float b0 = bias[c0], b1 = bias[c0 + 1];
        float* o0 = out + ((size_t)(b * C1 + c0) * OH1 + oh) * OW1;
        float* o1 = o0 + (size_t)OH1 * OW1;
#pragma unroll
        for (int j = 0; j < 8; ++j) {
            const int ow = tx + 16 * j;
            if (ow < OW1) {
                float lo, hi;
                unpack2(acc[m][j], lo, hi);
                o0[ow] = fmaxf(lo + b0, 0.0f);
                o1[ow] = fmaxf(hi + b1, 0.0f);
            }
        }
    }
}

// =====================================================================
// Kernel 2: conv2 (prim caps) + bias (NO relu).  out (B,256,9,12)
// GEMM: M=256 (c2) x N=108 (per-b positions) x K=25600.
// Block: fixed b, 64-channel tile. 256 threads (16x16), thread 4c2 x 7n.
// =====================================================================
__global__ __launch_bounds__(256)
void conv2_kernel(const float* __restrict__ relu1, const float* __restrict__ w2,
                  const float* __restrict__ pb, float* __restrict__ out) {
    __shared__ float s_w[16][64];
    __shared__ float s_b[16][112];

    const int tx = threadIdx.x & 15;
    const int ty = threadIdx.x >> 4;
    const int cb = blockIdx.x * 64;
    const int b  = blockIdx.y;

    float acc[4][7];
#pragma unroll
    for (int m = 0; m < 4; ++m)
#pragma unroll
        for (int j = 0; j < 7; ++j) acc[m][j] = 0.0f;

    const int wc = threadIdx.x >> 2;        // 0..63
    const int wk = (threadIdx.x & 3) * 4;   // 0,4,8,12
    const float* r1b = relu1 + (size_t)b * C1 * OH1 * OW1;

    for (int k0 = 0; k0 < KTOT2; k0 += 16) {
        __syncthreads();
        {   // weight tile
            float4 wv = *(const float4*)&w2[(size_t)(cb + wc) * KTOT2 + k0 + wk];
            s_w[wk + 0][wc] = wv.x;
            s_w[wk + 1][wc] = wv.y;
            s_w[wk + 2][wc] = wv.z;
            s_w[wk + 3][wc] = wv.w;
        }
        // B tile (im2col gather)
        for (int idx = threadIdx.x; idx < 16 * 112; idx += 256) {
            const int kk = idx / 112;
            const int nl = idx - kk * 112;
            float v = 0.0f;
            if (nl < 108) {
                const int k = k0 + kk;
                const int c1 = k / 100;
                const int r  = k - c1 * 100;
                const int kh = r / 10;
                const int kw = r - kh * 10;
                const int ohh = nl / 12;
                const int oww = nl - ohh * 12;
                v = r1b[((size_t)c1 * OH1 + ohh * 10 + kh) * OW1 + oww * 10 + kw];
            }
            s_b[kk][nl] = v;
        }
        __syncthreads();
#pragma unroll
        for (int kk = 0; kk < 16; ++kk) {
            float4 wv = *(const float4*)&s_w[kk][ty * 4];
            float xr[7];
#pragma unroll
            for (int j = 0; j < 7; ++j) xr[j] = s_b[kk][tx + 16 * j];
#pragma unroll
            for (int j = 0; j < 7; ++j) {
                acc[0][j] += wv.x * xr[j];
                acc[1][j] += wv.y * xr[j];
                acc[2][j] += wv.z * xr[j];
                acc[3][j] += wv.w * xr[j];
            }
        }
    }

#pragma unroll
    for (int m = 0; m < 4; ++m) {
        const int c2 = cb + ty * 4 + m;
        const float bb = pb[c2];
#pragma unroll
        for (int j = 0; j < 7; ++j) {
            const int nl = tx + 16 * j;
            if (nl < 108)
                out[((size_t)b * C2 + c2) * 108 + nl] = acc[m][j] + bb;
        }
    }
}

// =====================================================================
// Kernel 3: primary-caps squash + caps prediction (8 -> 80 per capsule)
// grid (NCAP, B), block 80: thread j computes up[b,i,j].
// capsule i = g*108 + p ; its 8 dims are channels g*8..g*8+7 at position p.
// =====================================================================
__global__ void squash_predict_kernel(const float* __restrict__ prim,
                                      const float* __restrict__ caps_w,
                                      float* __restrict__ up) {
    __shared__ float su[8];
    __shared__ float sfac;
    const int i = blockIdx.x;
    const int b = blockIdx.y;
    const int g = i / 108;
    const int p = i - g * 108;
    const int t = threadIdx.x;

    if (t < 8) su[t] = prim[((size_t)b * C2 + g * 8 + t) * 108 + p];
    __syncthreads();
    if (t == 0) {
        float l2 = 0.0f;
#pragma unroll
        for (int d = 0; d < 8; ++d) l2 += su[d] * su[d];
        sfac = sqrtf(l2) / (1.0f + l2);
    }
    __syncthreads();
    const float f = sfac;
    const float* cw = caps_w + (size_t)i * 8 * JD + t;
    float a = 0.0f;
#pragma unroll
    for (int d = 0; d < 8; ++d) a += su[d] * f * cw[d * JD];
    up[((size_t)b * NCAP + i) * JD + t] = a;
}

// =====================================================================
// Routing: s = sum_i c*up ; v = squash(s).  grid (NCLS, B), 256 threads.
// mode 0: c = softmax(b_route) (iteration 0);  mode 1: c from g_cc.
// =====================================================================
__global__ void route_s_kernel(const float* __restrict__ up,
                               const float* __restrict__ b_route,
                               const float* __restrict__ cmat,
                               float* __restrict__ vout, int mode) {
    const int o = blockIdx.x;
    const int b = blockIdx.y;
    const int t = threadIdx.x;
    const int lane = t & 31, wid = t >> 5;

    float sd[FD];
#pragma unroll
    for (int d = 0; d < FD; ++d) sd[d] = 0.0f;

    for (int i = t; i < NCAP; i += 256) {
        float ci;
        if (mode == 0) {
            float br[NCLS];
#pragma unroll
            for (int oo = 0; oo < NCLS; ++oo) br[oo] = b_route[i * NCLS + oo];
            float m = br[0];
#pragma unroll
            for (int oo = 1; oo < NCLS; ++oo) m = fmaxf(m, br[oo]);
            float s = 0.0f;
#pragma unroll
            for (int oo = 0; oo < NCLS; ++oo) s += expf(br[oo] - m);
            ci = expf(br[o] - m) / s;
        } else {
            ci = cmat[((size_t)b * NCAP + i) * NCLS + o];
        }
        const float* u = up + ((size_t)b * NCAP + i) * JD + o * FD;
#pragma unroll
        for (int d = 0; d < FD; ++d) sd[d] += ci * u[d];
    }
#pragma unroll
    for (int d = 0; d < FD; ++d)
        for (int off = 16; off; off >>= 1)
            sd[d] += __shfl_down_sync(0xffffffffu, sd[d], off);

    __shared__ float part[8][FD];
    __shared__ float fin[FD];
    __shared__ float fac;
    if (lane == 0)
#pragma unroll
        for (int d = 0; d < FD; ++d) part[wid][d] = sd[d];
    __syncthreads();
    if (t < FD) {
        float tot = 0.0f;
#pragma unroll
        for (int ww = 0; ww < 8; ++ww) tot += part[ww][t];
        fin[t] = tot;
    }
    __syncthreads();
    if (t == 0) {
        float l2 = 0.0f;
#pragma unroll
        for (int d = 0; d < FD; ++d) l2 += fin[d] * fin[d];
        fac = sqrtf(l2) / (1.0f + l2);
    }
    __syncthreads();
    if (t < FD) vout[((size_t)b * NCLS + o) * FD + t] = fin[t] * fac;
}

// =====================================================================
// Routing: b_batch += up.v ; c = softmax(b_batch).  one thread per (b,i)
// =====================================================================
__global__ void route_b_kernel(const float* __restrict__ up,
                               const float* __restrict__ b_route,
                               const float* __restrict__ v,
                               float* __restrict__ bb,
                               float* __restrict__ cmat, int first) {
    const int gid = blockIdx.x * blockDim.x + threadIdx.x;
    if (gid >= BATCH * NCAP) return;
    const int b = gid / NCAP;
    const int i = gid - b * NCAP;
    const float* u  = up + (size_t)gid * JD;
    const float* vb = v + (size_t)b * JD;

    float lg[NCLS];
#pragma unroll
    for (int o = 0; o < NCLS; ++o) {
        float dot = 0.0f;
#pragma unroll
        for (int d = 0; d < FD; ++d) dot += u[o * FD + d] * vb[o * FD + d];
        const float prev = first ? b_route[i * NCLS + o] : bb[(size_t)gid * NCLS + o];
        lg[o] = prev + dot;
        bb[(size_t)gid * NCLS + o] = lg[o];
    }
    float m = lg[0];
#pragma unroll
    for (int o = 1; o < NCLS; ++o) m = fmaxf(m, lg[o]);
    float s = 0.0f;
#pragma unroll
    for (int o = 0; o < NCLS; ++o) { lg[o] = expf(lg[o] - m); s += lg[o]; }
    const float inv = 1.0f / s;
#pragma unroll
    for (int o = 0; o < NCLS; ++o) cmat[(size_t)gid * NCLS + o] = lg[o] * inv;
}

// =====================================================================
// Heads: logits + log_softmax.  1 block, thread per (b,o).
// =====================================================================
__global__ void head_kernel(const float* __restrict__ v,
                            const float* __restrict__ pred_w,
                            const float* __restrict__ pred_b,
                            const float* __restrict__ eos_w,
                            const float* __restrict__ eos_b,
                            float* __restrict__ out) {
    const int t = threadIdx.x;
    if (t >= BATCH * NCLS) return;
    const float* vv = v + (size_t)t * FD;
    float lg[NREL + 1];
#pragma unroll 4
    for (int r = 0; r < NREL; ++r) {
        float a = pred_b[r];
#pragma unroll
        for (int d = 0; d < FD; ++d) a += vv[d] * pred_w[r * FD + d];
        lg[r] = a;
    }
    {
        float a = eos_b[0];
#pragma unroll
        for (int d = 0; d < FD; ++d) a += vv[d] * eos_w[d];
        lg[NREL] = a;
    }
    float m = lg[0];
#pragma unroll
    for (int k = 1; k <= NREL; ++k) m = fmaxf(m, lg[k]);
    float s = 0.0f;
#pragma unroll
    for (int k = 0; k <= NREL; ++k) s += expf(lg[k] - m);
    const float ls = m + logf(s);
#pragma unroll
    for (int k = 0; k <= NREL; ++k) out[(size_t)t * (NREL + 1) + k] = lg[k] - ls;
}

// =====================================================================
extern "C" void kernel_launch(void* const* d_in, const int* in_sizes, int n_in,
                              void* d_out, int out_size) {
    const float* input   = (const float*)d_in[0];
    const float* conv1_w = (const float*)d_in[1];
    const float* conv1_b = (const float*)d_in[2];
    const float* prim_w  = (const float*)d_in[3];
    const float* prim_b  = (const float*)d_in[4];
    const float* caps_w  = (const float*)d_in[5];
    const float* b_route = (const float*)d_in[6];
    const float* pred_w  = (const float*)d_in[7];
    const float* pred_b  = (const float*)d_in[8];
    const float* eos_w   = (const float*)d_in[9];
    const float* eos_b   = (const float*)d_in[10];
    float* out = (float*)d_out;

    float *conv1p, *primp, *upp, *bbp, *ccp, *vp;
    cudaGetSymbolAddress((void**)&conv1p, g_conv1);
    cudaGetSymbolAddress((void**)&primp, g_prim);
    cudaGetSymbolAddress((void**)&upp, g_up);
    cudaGetSymbolAddress((void**)&bbp, g_bb);
    cudaGetSymbolAddress((void**)&ccp, g_cc);
    cudaGetSymbolAddress((void**)&vp, g_v);

    // conv1 + relu
    conv1_kernel<<<dim3(2, OH1, BATCH), 256>>>(input, conv1_w, conv1_b, conv1p);
    // conv2 (prim caps)
    conv2_kernel<<<dim3(4, BATCH), 256>>>(conv1p, prim_w, prim_b, primp);
    // squash + caps prediction
    squash_predict_kernel<<<dim3(NCAP, BATCH), 80>>>(primp, caps_w, upp);
    // routing iteration 0 (uniform c from b_route)
    route_s_kernel<<<dim3(NCLS, BATCH), 256>>>(upp, b_route, ccp, vp, 0);
    for (int it = 0; it < 3; ++it) {
        route_b_kernel<<<(BATCH * NCAP + 255) / 256, 256>>>(upp, b_route, vp, bbp,
                                                            ccp, it == 0 ? 1 : 0);
        route_s_kernel<<<dim3(NCLS, BATCH), 256>>>(upp, b_route, ccp, vp, 1);
    }
    // heads + log_softmax
    head_kernel<<<1, BATCH * NCLS>>>(vp, pred_w, pred_b, eos_w, eos_b, out);
}

// round 5
// speedup vs baseline: 2.5597x; 2.5597x over previous
#include <cuda_runtime.h>
#include <cuda_fp16.h>
#include <math.h>
#include <stdint.h>

typedef unsigned short u16;

// ---------------- problem constants ----------------
#define BATCH 32
#define IH 120
#define IW 640
#define OH1 90            // only rows 0..89 consumed by conv2
#define C1 256
#define NCAP 3456
#define NCLS 5
#define FD 16
#define JD 80
#define NREL 25
#define K1 4800           // 30*160
#define K2 25600          // 100*256
#define NPOS 108          // 9*12

// ---------------- device scratch ----------------
__device__ u16 g_w1h[300 * 256 * 16];            // conv1 W hi  [step][c][k16]
__device__ u16 g_w1l[300 * 256 * 16];            // conv1 W lo
__device__ u16 g_w2h[256 * K2];                  // conv2 W hi  [c2][r*256+c1]
__device__ u16 g_w2l[256 * K2];
__device__ u16 g_c1h[(size_t)BATCH * NPOS * K2]; // conv1 out hi [b][pos][r*256+c]
__device__ u16 g_c1l[(size_t)BATCH * NPOS * K2];
__device__ float g_prim2[2][BATCH * 256 * NPOS]; // conv2 K-split partials
__device__ float g_up[BATCH * NCAP * JD];
__device__ float g_bb[BATCH * NCAP * NCLS];
__device__ float g_cc[BATCH * NCAP * NCLS];
__device__ float g_v[BATCH * NCLS * FD];

// ---------------- mma.sync m16n8k16 f16 -> f32 ----------------
__device__ __forceinline__ void mma16816(float* c, const uint32_t* a,
                                         const uint32_t* b) {
    asm volatile(
        "mma.sync.aligned.m16n8k16.row.col.f32.f16.f16.f32 "
        "{%0,%1,%2,%3}, {%4,%5,%6,%7}, {%8,%9}, {%0,%1,%2,%3};"
        : "+f"(c[0]), "+f"(c[1]), "+f"(c[2]), "+f"(c[3])
        : "r"(a[0]), "r"(a[1]), "r"(a[2]), "r"(a[3]), "r"(b[0]), "r"(b[1]));
}

__device__ __forceinline__ void split16(float v, u16& h, u16& l) {
    __half hh = __float2half_rn(v);
    h = __half_as_ushort(hh);
    l = __half_as_ushort(__float2half_rn(v - __half2float(hh)));
}

// =====================================================================
// prep conv1 weights: (256,1,30,160) fp32 -> [step=kh*10+kws][c][16] hi/lo
// =====================================================================
__global__ void prep_c1w(const float* __restrict__ w, u16* __restrict__ wh,
                         u16* __restrict__ wl) {
    int idx = blockIdx.x * 256 + threadIdx.x;          // 256*4800
    if (idx >= 256 * K1) return;
    int c = idx / K1;
    int k = idx - c * K1;
    int kh = k / 160, kw = k - kh * 160;
    int kws = kw >> 4, kk = kw & 15;
    int o = ((kh * 10 + kws) * 256 + c) * 16 + kk;
    split16(w[idx], wh[o], wl[o]);
}

// =====================================================================
// prep conv2 weights: (256,256,10,10) -> [c2][r*256+c1] hi/lo
// =====================================================================
__global__ void prep_c2w(const float* __restrict__ w2, u16* __restrict__ wh,
                         u16* __restrict__ wl) {
    int idx = blockIdx.x * 256 + threadIdx.x;          // 256*25600
    if (idx >= 256 * K2) return;
    int c2 = idx / K2;
    int k = idx - c2 * K2;
    int r = k >> 8, c1 = k & 255;
    split16(w2[(size_t)(c2 * 256 + c1) * 100 + r], wh[idx], wl[idx]);
}

// =====================================================================
// conv1 via HMMA: CTA = (mtile 128ch, oh, b), tile M128 x N128(ow) x K4800.
// 8 warps as 2(M) x 4(N), warp tile 64x32. fp16 split: hh + hl + lh.
// Output: relu, split to fp16 hi/lo in conv2 im2col order.
// =====================================================================
__global__ __launch_bounds__(256, 2)
void conv1_mma(const float* __restrict__ in, const u16* __restrict__ wh,
               const u16* __restrict__ wl, const float* __restrict__ bias,
               u16* __restrict__ c1h, u16* __restrict__ c1l) {
    __shared__ float s_row[IW];
    __shared__ u16 s_Ah[128 * 16], s_Al[128 * 16];
    __shared__ u16 s_Bh[128 * 16], s_Bl[128 * 16];

    const int tid = threadIdx.x;
    const int wid = tid >> 5, lane = tid & 31;
    const int grp = lane >> 2, tig = lane & 3;
    const int msub = wid & 1, nsub = wid >> 1;
    const int mt = blockIdx.x, oh = blockIdx.y, b = blockIdx.z;

    float acc[4][4][4] = {};

    const int ar = tid >> 1, ah8 = (tid & 1) * 8;      // A-copy row / 8-half
    uint4 rAh, rAl;
    {
        size_t off = ((size_t)0 * 256 + mt * 128 + ar) * 16 + ah8;
        rAh = *(const uint4*)(wh + off);
        rAl = *(const uint4*)(wl + off);
    }

    for (int kh = 0; kh < 30; ++kh) {
        {   // stage input row (safe: prior compute never reads s_row)
            const float4* src = (const float4*)(in + ((size_t)b * IH + oh + kh) * IW);
            for (int i = tid; i < IW / 4; i += 256) ((float4*)s_row)[i] = src[i];
        }
        for (int kws = 0; kws < 10; ++kws) {
            __syncthreads();                            // prior compute done
            *(uint4*)(s_Ah + ar * 16 + ah8) = rAh;
            *(uint4*)(s_Al + ar * 16 + ah8) = rAl;
#pragma unroll
            for (int e = 0; e < 8; ++e) {               // build B (im2col+split)
                int idx = tid + (e << 8);               // = n*16 + kk
                int n = idx >> 4, kk = idx & 15;
                int col = 4 * n + kws * 16 + kk;
                float v = s_row[col < IW ? col : IW - 1];
                split16(v, s_Bh[idx], s_Bl[idx]);
            }
            __syncthreads();
            const int step = kh * 10 + kws;
            if (step < 299) {                           // prefetch next A
                size_t off = ((size_t)(step + 1) * 256 + mt * 128 + ar) * 16 + ah8;
                rAh = *(const uint4*)(wh + off);
                rAl = *(const uint4*)(wl + off);
            }
            // compute
            uint32_t bh[4][2], bl[4][2];
#pragma unroll
            for (int nf = 0; nf < 4; ++nf) {
                int n0 = (nsub * 32 + nf * 8 + grp) * 16 + 2 * tig;
                bh[nf][0] = *(const uint32_t*)(s_Bh + n0);
                bh[nf][1] = *(const uint32_t*)(s_Bh + n0 + 8);
                bl[nf][0] = *(const uint32_t*)(s_Bl + n0);
                bl[nf][1] = *(const uint32_t*)(s_Bl + n0 + 8);
            }
#pragma unroll
            for (int mf = 0; mf < 4; ++mf) {
                const int m0 = msub * 64 + mf * 16;
                uint32_t a_h[4], a_l[4];
                a_h[0] = *(const uint32_t*)(s_Ah + (m0 + grp) * 16 + 2 * tig);
                a_h[1] = *(const uint32_t*)(s_Ah + (m0 + grp + 8) * 16 + 2 * tig);
                a_h[2] = *(const uint32_t*)(s_Ah + (m0 + grp) * 16 + 2 * tig + 8);
                a_h[3] = *(const uint32_t*)(s_Ah + (m0 + grp + 8) * 16 + 2 * tig + 8);
                a_l[0] = *(const uint32_t*)(s_Al + (m0 + grp) * 16 + 2 * tig);
                a_l[1] = *(const uint32_t*)(s_Al + (m0 + grp + 8) * 16 + 2 * tig);
                a_l[2] = *(const uint32_t*)(s_Al + (m0 + grp) * 16 + 2 * tig + 8);
                a_l[3] = *(const uint32_t*)(s_Al + (m0 + grp + 8) * 16 + 2 * tig + 8);
#pragma unroll
                for (int nf = 0; nf < 4; ++nf) {
                    mma16816(acc[mf][nf], a_h, bh[nf]);
                    mma16816(acc[mf][nf], a_h, bl[nf]);
                    mma16816(acc[mf][nf], a_l, bh[nf]);
                }
            }
        }
    }

    // epilogue: bias + relu + fp16 split, conv2 im2col order
    const int ohh = oh / 10, kh2 = oh - 10 * ohh;
#pragma unroll
    for (int mf = 0; mf < 4; ++mf) {
#pragma unroll
        for (int nf = 0; nf < 4; ++nf) {
#pragma unroll
            for (int i = 0; i < 4; ++i) {
                const int c = mt * 128 + msub * 64 + mf * 16 + grp + (i >> 1) * 8;
                const int ow = nsub * 32 + nf * 8 + 2 * tig + (i & 1);
                if (ow < 120) {
                    float v = fmaxf(acc[mf][nf][i] + bias[c], 0.0f);
                    int pos = ohh * 12 + ow / 10;
                    int r = kh2 * 10 + (ow % 10);
                    size_t o = (((size_t)b * NPOS + pos) * 100 + r) * 256 + c;
                    split16(v, c1h[o], c1l[o]);
                }
            }
        }
    }
}

// =====================================================================
// conv2 via HMMA: GEMM M=256(c2) x N=108(pos) x K=25600, 2-way K split.
// A = prepped w2 hi/lo; B = conv1 output hi/lo (already im2col order).
// =====================================================================
__global__ __launch_bounds__(256, 2)
void conv2_mma(const u16* __restrict__ c1h, const u16* __restrict__ c1l,
               const u16* __restrict__ w2h, const u16* __restrict__ w2l,
               const float* __restrict__ pb, float* __restrict__ prim2) {
    __shared__ u16 s_Ah[128 * 16], s_Al[128 * 16];
    __shared__ u16 s_Bh[128 * 16], s_Bl[128 * 16];

    const int tid = threadIdx.x;
    const int wid = tid >> 5, lane = tid & 31;
    const int grp = lane >> 2, tig = lane & 3;
    const int msub = wid & 1, nsub = wid >> 1;
    const int mt = blockIdx.x, b = blockIdx.y, ks = blockIdx.z;

    float acc[4][4][4] = {};

    const int ar = tid >> 1, ah8 = (tid & 1) * 8;
    const u16* Ah = w2h + (size_t)(mt * 128 + ar) * K2 + ah8;
    const u16* Al = w2l + (size_t)(mt * 128 + ar) * K2 + ah8;
    const u16* Bh = c1h + ((size_t)b * NPOS + ar) * K2 + ah8;
    const u16* Bl = c1l + ((size_t)b * NPOS + ar) * K2 + ah8;
    const bool bvalid = ar < NPOS;

    const int kbase = ks * (K2 / 2);
    uint4 rAh = *(const uint4*)(Ah + kbase);
    uint4 rAl = *(const uint4*)(Al + kbase);
    uint4 z = make_uint4(0, 0, 0, 0);
    uint4 rBh = bvalid ? *(const uint4*)(Bh + kbase) : z;
    uint4 rBl = bvalid ? *(const uint4*)(Bl + kbase) : z;

    for (int s = 0; s < 800; ++s) {
        __syncthreads();
        *(uint4*)(s_Ah + ar * 16 + ah8) = rAh;
        *(uint4*)(s_Al + ar * 16 + ah8) = rAl;
        *(uint4*)(s_Bh + ar * 16 + ah8) = rBh;
        *(uint4*)(s_Bl + ar * 16 + ah8) = rBl;
        __syncthreads();
        if (s < 799) {
            const int k = kbase + (s + 1) * 16;
            rAh = *(const uint4*)(Ah + k);
            rAl = *(const uint4*)(Al + k);
            rBh = bvalid ? *(const uint4*)(Bh + k) : z;
            rBl = bvalid ? *(const uint4*)(Bl + k) : z;
        }
        uint32_t bh[4][2], bl[4][2];
#pragma unroll
        for (int nf = 0; nf < 4; ++nf) {
            int n0 = (nsub * 32 + nf * 8 + grp) * 16 + 2 * tig;
            bh[nf][0] = *(const uint32_t*)(s_Bh + n0);
            bh[nf][1] = *(const uint32_t*)(s_Bh + n0 + 8);
            bl[nf][0] = *(const uint32_t*)(s_Bl + n0);
            bl[nf][1] = *(const uint32_t*)(s_Bl + n0 + 8);
        }
#pragma unroll
        for (int mf = 0; mf < 4; ++mf) {
            const int m0 = msub * 64 + mf * 16;
            uint32_t a_h[4], a_l[4];
            a_h[0] = *(const uint32_t*)(s_Ah + (m0 + grp) * 16 + 2 * tig);
            a_h[1] = *(const uint32_t*)(s_Ah + (m0 + grp + 8) * 16 + 2 * tig);
            a_h[2] = *(const uint32_t*)(s_Ah + (m0 + grp) * 16 + 2 * tig + 8);
            a_h[3] = *(const uint32_t*)(s_Ah + (m0 + grp + 8) * 16 + 2 * tig + 8);
            a_l[0] = *(const uint32_t*)(s_Al + (m0 + grp) * 16 + 2 * tig);
            a_l[1] = *(const uint32_t*)(s_Al + (m0 + grp + 8) * 16 + 2 * tig);
            a_l[2] = *(const uint32_t*)(s_Al + (m0 + grp) * 16 + 2 * tig + 8);
            a_l[3] = *(const uint32_t*)(s_Al + (m0 + grp + 8) * 16 + 2 * tig + 8);
#pragma unroll
            for (int nf = 0; nf < 4; ++nf) {
                mma16816(acc[mf][nf], a_h, bh[nf]);
                mma16816(acc[mf][nf], a_h, bl[nf]);
                mma16816(acc[mf][nf], a_l, bh[nf]);
            }
        }
    }

    float* outp = prim2 + (size_t)ks * (BATCH * 256 * NPOS);
#pragma unroll
    for (int mf = 0; mf < 4; ++mf) {
#pragma unroll
        for (int nf = 0; nf < 4; ++nf) {
#pragma unroll
            for (int i = 0; i < 4; ++i) {
                const int c2 = mt * 128 + msub * 64 + mf * 16 + grp + (i >> 1) * 8;
                const int n = nsub * 32 + nf * 8 + 2 * tig + (i & 1);
                if (n < NPOS) {
                    float v = acc[mf][nf][i] + (ks == 0 ? pb[c2] : 0.0f);
                    outp[((size_t)b * 256 + c2) * NPOS + n] = v;
                }
            }
        }
    }
}

// =====================================================================
// squash + caps prediction (sums the two conv2 partials)
// =====================================================================
__global__ void squash_predict_kernel(const float* __restrict__ prim2,
                                      const float* __restrict__ caps_w,
                                      float* __restrict__ up) {
    __shared__ float su[8];
    __shared__ float sfac;
    const int i = blockIdx.x;
    const int b = blockIdx.y;
    const int g = i / NPOS;
    const int p = i - g * NPOS;
    const int t = threadIdx.x;
    const float* pa = prim2;
    const float* pbv = prim2 + BATCH * 256 * NPOS;

    if (t < 8) {
        size_t o = ((size_t)b * 256 + g * 8 + t) * NPOS + p;
        su[t] = pa[o] + pbv[o];
    }
    __syncthreads();
    if (t == 0) {
        float l2 = 0.0f;
#pragma unroll
        for (int d = 0; d < 8; ++d) l2 += su[d] * su[d];
        sfac = sqrtf(l2) / (1.0f + l2);
    }
    __syncthreads();
    const float f = sfac;
    const float* cw = caps_w + (size_t)i * 8 * JD + t;
    float a = 0.0f;
#pragma unroll
    for (int d = 0; d < 8; ++d) a += su[d] * f * cw[d * JD];
    up[((size_t)b * NCAP + i) * JD + t] = a;
}

// =====================================================================
// routing s/v
// =====================================================================
__global__ void route_s_kernel(const float* __restrict__ up,
                               const float* __restrict__ b_route,
                               const float* __restrict__ cmat,
                               float* __restrict__ vout, int mode) {
    const int o = blockIdx.x;
    const int b = blockIdx.y;
    const int t = threadIdx.x;
    const int lane = t & 31, wid = t >> 5;

    float sd[FD];
#pragma unroll
    for (int d = 0; d < FD; ++d) sd[d] = 0.0f;

    for (int i = t; i < NCAP; i += 256) {
        float ci;
        if (mode == 0) {
            float br[NCLS];
#pragma unroll
            for (int oo = 0; oo < NCLS; ++oo) br[oo] = b_route[i * NCLS + oo];
            float m = br[0];
#pragma unroll
            for (int oo = 1; oo < NCLS; ++oo) m = fmaxf(m, br[oo]);
            float s = 0.0f;
#pragma unroll
            for (int oo = 0; oo < NCLS; ++oo) s += expf(br[oo] - m);
            ci = expf(br[o] - m) / s;
        } else {
            ci = cmat[((size_t)b * NCAP + i) * NCLS + o];
        }
        const float* u = up + ((size_t)b * NCAP + i) * JD + o * FD;
#pragma unroll
        for (int d = 0; d < FD; ++d) sd[d] += ci * u[d];
    }
#pragma unroll
    for (int d = 0; d < FD; ++d)
        for (int off = 16; off; off >>= 1)
            sd[d] += __shfl_down_sync(0xffffffffu, sd[d], off);

    __shared__ float part[8][FD];
    __shared__ float fin[FD];
    __shared__ float fac;
    if (lane == 0)
#pragma unroll
        for (int d = 0; d < FD; ++d) part[wid][d] = sd[d];
    __syncthreads();
    if (t < FD) {
        float tot = 0.0f;
#pragma unroll
        for (int ww = 0; ww < 8; ++ww) tot += part[ww][t];
        fin[t] = tot;
    }
    __syncthreads();
    if (t == 0) {
        float l2 = 0.0f;
#pragma unroll
        for (int d = 0; d < FD; ++d) l2 += fin[d] * fin[d];
        fac = sqrtf(l2) / (1.0f + l2);
    }
    __syncthreads();
    if (t < FD) vout[((size_t)b * NCLS + o) * FD + t] = fin[t] * fac;
}

// =====================================================================
// routing b/c update
// =====================================================================
__global__ void route_b_kernel(const float* __restrict__ up,
                               const float* __restrict__ b_route,
                               const float* __restrict__ v,
                               float* __restrict__ bb,
                               float* __restrict__ cmat, int first) {
    const int gid = blockIdx.x * blockDim.x + threadIdx.x;
    if (gid >= BATCH * NCAP) return;
    const int b = gid / NCAP;
    const int i = gid - b * NCAP;
    const float* u = up + (size_t)gid * JD;
    const float* vb = v + (size_t)b * JD;

    float lg[NCLS];
#pragma unroll
    for (int o = 0; o < NCLS; ++o) {
        float dot = 0.0f;
#pragma unroll
        for (int d = 0; d < FD; ++d) dot += u[o * FD + d] * vb[o * FD + d];
        const float prev = first ? b_route[i * NCLS + o] : bb[(size_t)gid * NCLS + o];
        lg[o] = prev + dot;
        bb[(size_t)gid * NCLS + o] = lg[o];
    }
    float m = lg[0];
#pragma unroll
    for (int o = 1; o < NCLS; ++o) m = fmaxf(m, lg[o]);
    float s = 0.0f;
#pragma unroll
    for (int o = 0; o < NCLS; ++o) { lg[o] = expf(lg[o] - m); s += lg[o]; }
    const float inv = 1.0f / s;
#pragma unroll
    for (int o = 0; o < NCLS; ++o) cmat[(size_t)gid * NCLS + o] = lg[o] * inv;
}

// =====================================================================
// heads
// =====================================================================
__global__ void head_kernel(const float* __restrict__ v,
                            const float* __restrict__ pred_w,
                            const float* __restrict__ pred_b,
                            const float* __restrict__ eos_w,
                            const float* __restrict__ eos_b,
                            float* __restrict__ out) {
    const int t = threadIdx.x;
    if (t >= BATCH * NCLS) return;
    const float* vv = v + (size_t)t * FD;
    float lg[NREL + 1];
#pragma unroll 4
    for (int r = 0; r < NREL; ++r) {
        float a = pred_b[r];
#pragma unroll
        for (int d = 0; d < FD; ++d) a += vv[d] * pred_w[r * FD + d];
        lg[r] = a;
    }
    {
        float a = eos_b[0];
#pragma unroll
        for (int d = 0; d < FD; ++d) a += vv[d] * eos_w[d];
        lg[NREL] = a;
    }
    float m = lg[0];
#pragma unroll
    for (int k = 1; k <= NREL; ++k) m = fmaxf(m, lg[k]);
    float s = 0.0f;
#pragma unroll
    for (int k = 0; k <= NREL; ++k) s += expf(lg[k] - m);
    const float ls = m + logf(s);
#pragma unroll
    for (int k = 0; k <= NREL; ++k) out[(size_t)t * (NREL + 1) + k] = lg[k] - ls;
}

// =====================================================================
extern "C" void kernel_launch(void* const* d_in, const int* in_sizes, int n_in,
                              void* d_out, int out_size) {
    const float* input   = (const float*)d_in[0];
    const float* conv1_w = (const float*)d_in[1];
    const float* conv1_b = (const float*)d_in[2];
    const float* prim_w  = (const float*)d_in[3];
    const float* prim_b  = (const float*)d_in[4];
    const float* caps_w  = (const float*)d_in[5];
    const float* b_route = (const float*)d_in[6];
    const float* pred_w  = (const float*)d_in[7];
    const float* pred_b  = (const float*)d_in[8];
    const float* eos_w   = (const float*)d_in[9];
    const float* eos_b   = (const float*)d_in[10];
    float* out = (float*)d_out;

    u16 *w1h, *w1l, *w2h, *w2l, *c1h, *c1l;
    float *prim2, *upp, *bbp, *ccp, *vp;
    cudaGetSymbolAddress((void**)&w1h, g_w1h);
    cudaGetSymbolAddress((void**)&w1l, g_w1l);
    cudaGetSymbolAddress((void**)&w2h, g_w2h);
    cudaGetSymbolAddress((void**)&w2l, g_w2l);
    cudaGetSymbolAddress((void**)&c1h, g_c1h);
    cudaGetSymbolAddress((void**)&c1l, g_c1l);
    cudaGetSymbolAddress((void**)&prim2, g_prim2);
    cudaGetSymbolAddress((void**)&upp, g_up);
    cudaGetSymbolAddress((void**)&bbp, g_bb);
    cudaGetSymbolAddress((void**)&ccp, g_cc);
    cudaGetSymbolAddress((void**)&vp, g_v);

    prep_c1w<<<(256 * K1 + 255) / 256, 256>>>(conv1_w, w1h, w1l);
    prep_c2w<<<(256 * K2 + 255) / 256, 256>>>(prim_w, w2h, w2l);
    conv1_mma<<<dim3(2, OH1, BATCH), 256>>>(input, w1h, w1l, conv1_b, c1h, c1l);
    conv2_mma<<<dim3(2, BATCH, 2), 256>>>(c1h, c1l, w2h, w2l, prim_b, prim2);
    squash_predict_kernel<<<dim3(NCAP, BATCH), 80>>>(prim2, caps_w, upp);
    route_s_kernel<<<dim3(NCLS, BATCH), 256>>>(upp, b_route, ccp, vp, 0);
    for (int it = 0; it < 3; ++it) {
        route_b_kernel<<<(BATCH * NCAP + 255) / 256, 256>>>(upp, b_route, vp, bbp,
                                                            ccp, it == 0 ? 1 : 0);
        route_s_kernel<<<dim3(NCLS, BATCH), 256>>>(upp, b_route, ccp, vp, 1);
    }
    head_kernel<<<1, BATCH * NCLS>>>(vp, pred_w, pred_b, eos_w, eos_b, out);
}

// round 6
// speedup vs baseline: 3.0190x; 1.1795x over previous
#include <cuda_runtime.h>
#include <cuda_fp16.h>
#include <math.h>
#include <stdint.h>

typedef unsigned short u16;

// ---------------- problem constants ----------------
#define BATCH 32
#define IH 120
#define IW 640
#define PADW 688          // padded input width (fp16 split arrays)
#define OH1 90            // only rows 0..89 consumed by conv2
#define NCAP 3456
#define NCLS 5
#define FD 16
#define JD 80
#define NREL 25
#define K1 4800
#define K2 25600
#define NPOS 108
#define KSPLIT 4

// ---------------- device scratch ----------------
__device__ u16 g_inh[(size_t)BATCH * IH * PADW];
__device__ u16 g_inl[(size_t)BATCH * IH * PADW];
__device__ u16 g_w1h[300 * 256 * 16];            // conv1 W hi [step][c][k16]
__device__ u16 g_w1l[300 * 256 * 16];
__device__ u16 g_w2h[256 * K2];                  // conv2 W [c2][r*256+c1]
__device__ u16 g_w2l[256 * K2];
__device__ u16 g_c1h[(size_t)BATCH * NPOS * K2]; // conv1 out [b][pos][r*256+c]
__device__ u16 g_c1l[(size_t)BATCH * NPOS * K2];
__device__ float g_prim4[KSPLIT][BATCH * 256 * NPOS];
__device__ float g_up[BATCH * NCAP * JD];
__device__ float g_bb[2][BATCH * NCAP * NCLS];
__device__ float g_v[2][BATCH * NCLS * FD];

// ---------------- helpers ----------------
__device__ __forceinline__ void mma16816(float* c, const uint32_t* a,
                                         const uint32_t* b) {
    asm volatile(
        "mma.sync.aligned.m16n8k16.row.col.f32.f16.f16.f32 "
        "{%0,%1,%2,%3}, {%4,%5,%6,%7}, {%8,%9}, {%0,%1,%2,%3};"
        : "+f"(c[0]), "+f"(c[1]), "+f"(c[2]), "+f"(c[3])
        : "r"(a[0]), "r"(a[1]), "r"(a[2]), "r"(a[3]), "r"(b[0]), "r"(b[1]));
}
__device__ __forceinline__ void split16(float v, u16& h, u16& l) {
    __half hh = __float2half_rn(v);
    h = __half_as_ushort(hh);
    l = __half_as_ushort(__float2half_rn(v - __half2float(hh)));
}
__device__ __forceinline__ void cp16(uint32_t dst, const void* src) {
    asm volatile("cp.async.ca.shared.global [%0], [%1], 16;"
                 :: "r"(dst), "l"(src));
}
__device__ __forceinline__ void cp_commit() {
    asm volatile("cp.async.commit_group;");
}
__device__ __forceinline__ void cp_wait0() {
    asm volatile("cp.async.wait_group 0;");
}

// =====================================================================
// prep: split input to fp16 hi/lo, padded rows (cols 640..687 = 0)
// =====================================================================
__global__ void prep_in(const float* __restrict__ in, u16* __restrict__ ih,
                        u16* __restrict__ il) {
    int idx = blockIdx.x * 256 + threadIdx.x;
    if (idx >= BATCH * IH * PADW) return;
    int col = idx % PADW;
    int rb = idx / PADW;                 // b*IH + row
    float v = (col < IW) ? in[(size_t)rb * IW + col] : 0.0f;
    split16(v, ih[idx], il[idx]);
}

// =====================================================================
// prep conv1 weights: (256,1,30,160) fp32 -> [step=kh*10+kws][c][16]
// =====================================================================
__global__ void prep_c1w(const float* __restrict__ w, u16* __restrict__ wh,
                         u16* __restrict__ wl) {
    int idx = blockIdx.x * 256 + threadIdx.x;
    if (idx >= 256 * K1) return;
    int c = idx / K1;
    int k = idx - c * K1;
    int kh = k / 160, kw = k - kh * 160;
    int kws = kw >> 4, kk = kw & 15;
    int o = ((kh * 10 + kws) * 256 + c) * 16 + kk;
    split16(w[idx], wh[o], wl[o]);
}

// =====================================================================
// prep conv2 weights: (256,256,10,10) -> [c2][r*256+c1]
// =====================================================================
__global__ void prep_c2w(const float* __restrict__ w2, u16* __restrict__ wh,
                         u16* __restrict__ wl) {
    int idx = blockIdx.x * 256 + threadIdx.x;
    if (idx >= 256 * K2) return;
    int c2 = idx / K2;
    int k = idx - c2 * K2;
    int r = k >> 8, c1 = k & 255;
    split16(w2[(size_t)(c2 * 256 + c1) * 100 + r], wh[idx], wl[idx]);
}

// =====================================================================
// conv1 via HMMA: CTA = (oh, b), tile M256 x N128(ow) x K4800.
// 8 warps 4(M)x2(N), warp tile 64x64. A smem (swizzled, cp.async double
// buffer, 1 sync/step); B fragments direct from pre-split gmem rows.
// =====================================================================
__global__ __launch_bounds__(256, 1)
void conv1_mma(const u16* __restrict__ inh, const u16* __restrict__ inl,
               const u16* __restrict__ w1h, const u16* __restrict__ w1l,
               const float* __restrict__ bias,
               u16* __restrict__ c1h, u16* __restrict__ c1l) {
    // [stage][h/l][256 rows x 8 u32], halves XOR-swizzled by (c>>2)&1
    __shared__ uint32_t sA[2][2][2048];

    const int tid = threadIdx.x;
    const int wid = tid >> 5, lane = tid & 31;
    const int grp = lane >> 2, tig = lane & 3;
    const int wm = wid >> 1, wn = wid & 1;
    const int oh = blockIdx.x, b = blockIdx.y;

    float acc[4][8][4] = {};

    const int swd = (tid >> 2) & 1;          // this thread's A-copy row = tid
    const uint32_t sA0 = (uint32_t)__cvta_generic_to_shared(&sA[0][0][0]);

    // stage A(step) into buffer stg via cp.async (4x16B per thread)
    auto stageA = [&](int step, int stg) {
        const u16* sh = w1h + ((size_t)step * 256 + tid) * 16;
        const u16* sl = w1l + ((size_t)step * 256 + tid) * 16;
        uint32_t bh = sA0 + (stg * 2 + 0) * 8192 + tid * 32;
        uint32_t bl = sA0 + (stg * 2 + 1) * 8192 + tid * 32;
        cp16(bh + ((0 ^ swd) << 4), sh);
        cp16(bh + ((1 ^ swd) << 4), sh + 8);
        cp16(bl + ((0 ^ swd) << 4), sl);
        cp16(bl + ((1 ^ swd) << 4), sl + 8);
        cp_commit();
    };

    stageA(0, 0);
    cp_wait0();
    __syncthreads();

    int kh = 0, kws = 0;
    for (int step = 0; step < 300; ++step) {
        const int stg = step & 1;
        if (step < 299) stageA(step + 1, stg ^ 1);

        // B fragments straight from gmem (pre-split, padded rows)
        const u16* rh = inh + ((size_t)(b * IH + oh + kh)) * PADW + 16 * kws;
        const u16* rl = inl + ((size_t)(b * IH + oh + kh)) * PADW + 16 * kws;
        uint32_t bh[8][2], bl[8][2];
#pragma unroll
        for (int nf = 0; nf < 8; ++nf) {
            const int cb = 4 * (wn * 64 + nf * 8 + grp) + 2 * tig;
            bh[nf][0] = *(const uint32_t*)(rh + cb);
            bh[nf][1] = *(const uint32_t*)(rh + cb + 8);
            bl[nf][0] = *(const uint32_t*)(rl + cb);
            bl[nf][1] = *(const uint32_t*)(rl + cb + 8);
        }
#pragma unroll
        for (int mf = 0; mf < 4; ++mf) {
            const int c0 = wm * 64 + mf * 16 + grp;     // rows c0, c0+8
            const int sw = ((c0 >> 2) & 1) << 2;        // u32-swizzle (4 words)
            const uint32_t* Ah = sA[stg][0];
            const uint32_t* Al = sA[stg][1];
            uint32_t a_h[4], a_l[4];
            a_h[0] = Ah[c0 * 8 + (0 ^ sw) + tig];
            a_h[1] = Ah[(c0 + 8) * 8 + (0 ^ sw) + tig];
            a_h[2] = Ah[c0 * 8 + (4 ^ sw) + tig];
            a_h[3] = Ah[(c0 + 8) * 8 + (4 ^ sw) + tig];
            a_l[0] = Al[c0 * 8 + (0 ^ sw) + tig];
            a_l[1] = Al[(c0 + 8) * 8 + (0 ^ sw) + tig];
            a_l[2] = Al[c0 * 8 + (4 ^ sw) + tig];
            a_l[3] = Al[(c0 + 8) * 8 + (4 ^ sw) + tig];
#pragma unroll
            for (int nf = 0; nf < 8; ++nf) {
                mma16816(acc[mf][nf], a_h, bh[nf]);
                mma16816(acc[mf][nf], a_h, bl[nf]);
                mma16816(acc[mf][nf], a_l, bh[nf]);
            }
        }
        cp_wait0();
        __syncthreads();
        if (++kws == 10) { kws = 0; ++kh; }
    }

    // epilogue: bias + relu + fp16 split, conv2 im2col order
    const int ohh = oh / 10, kh2 = oh - 10 * ohh;
#pragma unroll
    for (int mf = 0; mf < 4; ++mf) {
#pragma unroll
        for (int nf = 0; nf < 8; ++nf) {
#pragma unroll
            for (int i = 0; i < 4; ++i) {
                const int c = wm * 64 + mf * 16 + grp + (i >> 1) * 8;
                const int ow = wn * 64 + nf * 8 + 2 * tig + (i & 1);
                if (ow < 120) {
                    float v = fmaxf(acc[mf][nf][i] + bias[c], 0.0f);
                    int pos = ohh * 12 + ow / 10;
                    int r = kh2 * 10 + (ow % 10);
                    size_t o = (((size_t)b * NPOS + pos) * 100 + r) * 256 + c;
                    split16(v, c1h[o], c1l[o]);
                }
            }
        }
    }
}

// =====================================================================
// conv2 via HMMA: GEMM M=256 x N=108 x K=25600, 4-way K split.
// =====================================================================
__global__ __launch_bounds__(256, 2)
void conv2_mma(const u16* __restrict__ c1h, const u16* __restrict__ c1l,
               const u16* __restrict__ w2h, const u16* __restrict__ w2l,
               const float* __restrict__ pb, float* __restrict__ prim4) {
    __shared__ u16 s_Ah[128 * 16], s_Al[128 * 16];
    __shared__ u16 s_Bh[128 * 16], s_Bl[128 * 16];

    const int tid = threadIdx.x;
    const int wid = tid >> 5, lane = tid & 31;
    const int grp = lane >> 2, tig = lane & 3;
    const int msub = wid & 1, nsub = wid >> 1;
    const int mt = blockIdx.x, b = blockIdx.y, ks = blockIdx.z;

    float acc[4][4][4] = {};

    const int ar = tid >> 1, ah8 = (tid & 1) * 8;
    const u16* Ah = w2h + (size_t)(mt * 128 + ar) * K2 + ah8;
    const u16* Al = w2l + (size_t)(mt * 128 + ar) * K2 + ah8;
    const u16* Bh = c1h + ((size_t)b * NPOS + ar) * K2 + ah8;
    const u16* Bl = c1l + ((size_t)b * NPOS + ar) * K2 + ah8;
    const bool bvalid = ar < NPOS;

    const int kbase = ks * (K2 / KSPLIT);
    const int NSTEP = K2 / KSPLIT / 16;              // 400
    uint4 rAh = *(const uint4*)(Ah + kbase);
    uint4 rAl = *(const uint4*)(Al + kbase);
    uint4 z = make_uint4(0, 0, 0, 0);
    uint4 rBh = bvalid ? *(const uint4*)(Bh + kbase) : z;
    uint4 rBl = bvalid ? *(const uint4*)(Bl + kbase) : z;

    for (int s = 0; s < NSTEP; ++s) {
        __syncthreads();
        *(uint4*)(s_Ah + ar * 16 + ah8) = rAh;
        *(uint4*)(s_Al + ar * 16 + ah8) = rAl;
        *(uint4*)(s_Bh + ar * 16 + ah8) = rBh;
        *(uint4*)(s_Bl + ar * 16 + ah8) = rBl;
        __syncthreads();
        if (s < NSTEP - 1) {
            const int k = kbase + (s + 1) * 16;
            rAh = *(const uint4*)(Ah + k);
            rAl = *(const uint4*)(Al + k);
            rBh = bvalid ? *(const uint4*)(Bh + k) : z;
            rBl = bvalid ? *(const uint4*)(Bl + k) : z;
        }
        uint32_t bh[4][2], bl[4][2];
#pragma unroll
        for (int nf = 0; nf < 4; ++nf) {
            int n0 = (nsub * 32 + nf * 8 + grp) * 16 + 2 * tig;
            bh[nf][0] = *(const uint32_t*)(s_Bh + n0);
            bh[nf][1] = *(const uint32_t*)(s_Bh + n0 + 8);
            bl[nf][0] = *(const uint32_t*)(s_Bl + n0);
            bl[nf][1] = *(const uint32_t*)(s_Bl + n0 + 8);
        }
#pragma unroll
        for (int mf = 0; mf < 4; ++mf) {
            const int m0 = msub * 64 + mf * 16;
            uint32_t a_h[4], a_l[4];
            a_h[0] = *(const uint32_t*)(s_Ah + (m0 + grp) * 16 + 2 * tig);
            a_h[1] = *(const uint32_t*)(s_Ah + (m0 + grp + 8) * 16 + 2 * tig);
            a_h[2] = *(const uint32_t*)(s_Ah + (m0 + grp) * 16 + 2 * tig + 8);
            a_h[3] = *(const uint32_t*)(s_Ah + (m0 + grp + 8) * 16 + 2 * tig + 8);
            a_l[0] = *(const uint32_t*)(s_Al + (m0 + grp) * 16 + 2 * tig);
            a_l[1] = *(const uint32_t*)(s_Al + (m0 + grp + 8) * 16 + 2 * tig);
            a_l[2] = *(const uint32_t*)(s_Al + (m0 + grp) * 16 + 2 * tig + 8);
            a_l[3] = *(const uint32_t*)(s_Al + (m0 + grp + 8) * 16 + 2 * tig + 8);
#pragma unroll
            for (int nf = 0; nf < 4; ++nf) {
                mma16816(acc[mf][nf], a_h, bh[nf]);
                mma16816(acc[mf][nf], a_h, bl[nf]);
                mma16816(acc[mf][nf], a_l, bh[nf]);
            }
        }
    }

    float* outp = prim4 + (size_t)ks * (BATCH * 256 * NPOS);
#pragma unroll
    for (int mf = 0; mf < 4; ++mf) {
#pragma unroll
        for (int nf = 0; nf < 4; ++nf) {
#pragma unroll
            for (int i = 0; i < 4; ++i) {
                const int c2 = mt * 128 + msub * 64 + mf * 16 + grp + (i >> 1) * 8;
                const int n = nsub * 32 + nf * 8 + 2 * tig + (i & 1);
                if (n < NPOS) {
                    float v = acc[mf][nf][i] + (ks == 0 ? pb[c2] : 0.0f);
                    outp[((size_t)b * 256 + c2) * NPOS + n] = v;
                }
            }
        }
    }
}

// =====================================================================
// squash + caps prediction (sums 4 conv2 partials)
// =====================================================================
__global__ void squash_predict_kernel(const float* __restrict__ prim4,
                                      const float* __restrict__ caps_w,
                                      float* __restrict__ up) {
    __shared__ float su[8];
    __shared__ float sfac;
    const int i = blockIdx.x;
    const int b = blockIdx.y;
    const int g = i / NPOS;
    const int p = i - g * NPOS;
    const int t = threadIdx.x;
    const int SL = BATCH * 256 * NPOS;

    if (t < 8) {
        size_t o = ((size_t)b * 256 + g * 8 + t) * NPOS + p;
        su[t] = prim4[o] + prim4[o + SL] + prim4[o + 2 * SL] + prim4[o + 3 * SL];
    }
    __syncthreads();
    if (t == 0) {
        float l2 = 0.0f;
#pragma unroll
        for (int d = 0; d < 8; ++d) l2 += su[d] * su[d];
        sfac = sqrtf(l2) / (1.0f + l2);
    }
    __syncthreads();
    const float f = sfac;
    const float* cw = caps_w + (size_t)i * 8 * JD + t;
    float a = 0.0f;
#pragma unroll
    for (int d = 0; d < 8; ++d) a += su[d] * f * cw[d * JD];
    up[((size_t)b * NCAP + i) * JD + t] = a;
}

// =====================================================================
// routing iteration 0: c = softmax(b_route); s = sum c*u; v = squash(s)
// =====================================================================
__global__ void route_s0_kernel(const float* __restrict__ up,
                                const float* __restrict__ b_route,
                                float* __restrict__ vout) {
    const int o = blockIdx.x;
    const int b = blockIdx.y;
    const int t = threadIdx.x;
    const int lane = t & 31, wid = t >> 5;

    float sd[FD];
#pragma unroll
    for (int d = 0; d < FD; ++d) sd[d] = 0.0f;

    for (int i = t; i < NCAP; i += 256) {
        float br[NCLS];
#pragma unroll
        for (int oo = 0; oo < NCLS; ++oo) br[oo] = b_route[i * NCLS + oo];
        float m = br[0];
#pragma unroll
        for (int oo = 1; oo < NCLS; ++oo) m = fmaxf(m, br[oo]);
        float s = 0.0f;
#pragma unroll
        for (int oo = 0; oo < NCLS; ++oo) s += expf(br[oo] - m);
        float ci = expf(br[o] - m) / s;
        const float* u = up + ((size_t)b * NCAP + i) * JD + o * FD;
#pragma unroll
        for (int d = 0; d < FD; ++d) sd[d] += ci * u[d];
    }
#pragma unroll
    for (int d = 0; d < FD; ++d)
        for (int off = 16; off; off >>= 1)
            sd[d] += __shfl_down_sync(0xffffffffu, sd[d], off);

    __shared__ float part[8][FD];
    __shared__ float fin[FD];
    __shared__ float fac;
    if (lane == 0)
#pragma unroll
        for (int d = 0; d < FD; ++d) part[wid][d] = sd[d];
    __syncthreads();
    if (t < FD) {
        float tot = 0.0f;
#pragma unroll
        for (int ww = 0; ww < 8; ++ww) tot += part[ww][t];
        fin[t] = tot;
    }
    __syncthreads();
    if (t == 0) {
        float l2 = 0.0f;
#pragma unroll
        for (int d = 0; d < FD; ++d) l2 += fin[d] * fin[d];
        fac = sqrtf(l2) / (1.0f + l2);
    }
    __syncthreads();
    if (t < FD) vout[((size_t)b * NCLS + o) * FD + t] = fin[t] * fac;
}

// =====================================================================
// fused routing iteration: b += u.v; c = softmax(b); s = sum c*u;
// v = squash(s). Double-buffered bb and v (no intra-kernel races).
// =====================================================================
__global__ void route_fused(const float* __restrict__ up,
                            const float* __restrict__ b_route,
                            const float* __restrict__ vin,
                            float* __restrict__ vout,
                            const float* __restrict__ bb_rd,
                            float* __restrict__ bb_wr, int first) {
    const int o = blockIdx.x;
    const int b = blockIdx.y;
    const int t = threadIdx.x;
    const int lane = t & 31, wid = t >> 5;

    __shared__ float sv[JD];
    if (t < JD) sv[t] = vin[b * JD + t];
    __syncthreads();

    float sd[FD];
#pragma unroll
    for (int d = 0; d < FD; ++d) sd[d] = 0.0f;

    for (int i = t; i < NCAP; i += 256) {
        const size_t base = ((size_t)b * NCAP + i);
        float u[JD];
        const float4* u4 = (const float4*)(up + base * JD);
#pragma unroll
        for (int q = 0; q < JD / 4; ++q) {
            float4 vv = u4[q];
            u[4 * q] = vv.x; u[4 * q + 1] = vv.y;
            u[4 * q + 2] = vv.z; u[4 * q + 3] = vv.w;
        }
        float nb[NCLS];
#pragma unroll
        for (int oo = 0; oo < NCLS; ++oo) {
            float dot = 0.0f;
#pragma unroll
            for (int d = 0; d < FD; ++d) dot += u[oo * FD + d] * sv[oo * FD + d];
            float prev = first ? b_route[i * NCLS + oo] : bb_rd[base * NCLS + oo];
            nb[oo] = prev + dot;
        }
        if (o == 0) {
#pragma unroll
            for (int oo = 0; oo < NCLS; ++oo) bb_wr[base * NCLS + oo] = nb[oo];
        }
        float m = nb[0];
#pragma unroll
        for (int oo = 1; oo < NCLS; ++oo) m = fmaxf(m, nb[oo]);
        float s = 0.0f;
#pragma unroll
        for (int oo = 0; oo < NCLS; ++oo) s += expf(nb[oo] - m);
        float ci = expf(nb[o] - m) / s;
#pragma unroll
        for (int d = 0; d < FD; ++d) sd[d] += ci * u[o * FD + d];
    }
#pragma unroll
    for (int d = 0; d < FD; ++d)
        for (int off = 16; off; off >>= 1)
            sd[d] += __shfl_down_sync(0xffffffffu, sd[d], off);

    __shared__ float part[8][FD];
    __shared__ float fin[FD];
    __shared__ float fac;
    if (lane == 0)
#pragma unroll
        for (int d = 0; d < FD; ++d) part[wid][d] = sd[d];
    __syncthreads();
    if (t < FD) {
        float tot = 0.0f;
#pragma unroll
        for (int ww = 0; ww < 8; ++ww) tot += part[ww][t];
        fin[t] = tot;
    }
    __syncthreads();
    if (t == 0) {
        float l2 = 0.0f;
#pragma unroll
        for (int d = 0; d < FD; ++d) l2 += fin[d] * fin[d];
        fac = sqrtf(l2) / (1.0f + l2);
    }
    __syncthreads();
    if (t < FD) vout[((size_t)b * NCLS + o) * FD + t] = fin[t] * fac;
}

// =====================================================================
// heads
// =====================================================================
__global__ void head_kernel(const float* __restrict__ v,
                            const float* __restrict__ pred_w,
                            const float* __restrict__ pred_b,
                            const float* __restrict__ eos_w,
                            const float* __restrict__ eos_b,
                            float* __restrict__ out) {
    const int t = threadIdx.x;
    if (t >= BATCH * NCLS) return;
    const float* vv = v + (size_t)t * FD;
    float lg[NREL + 1];
#pragma unroll 4
    for (int r = 0; r < NREL; ++r) {
        float a = pred_b[r];
#pragma unroll
        for (int d = 0; d < FD; ++d) a += vv[d] * pred_w[r * FD + d];
        lg[r] = a;
    }
    {
        float a = eos_b[0];
#pragma unroll
        for (int d = 0; d < FD; ++d) a += vv[d] * eos_w[d];
        lg[NREL] = a;
    }
    float m = lg[0];
#pragma unroll
    for (int k = 1; k <= NREL; ++k) m = fmaxf(m, lg[k]);
    float s = 0.0f;
#pragma unroll
    for (int k = 0; k <= NREL; ++k) s += expf(lg[k] - m);
    const float ls = m + logf(s);
#pragma unroll
    for (int k = 0; k <= NREL; ++k) out[(size_t)t * (NREL + 1) + k] = lg[k] - ls;
}

// =====================================================================
extern "C" void kernel_launch(void* const* d_in, const int* in_sizes, int n_in,
                              void* d_out, int out_size) {
    const float* input   = (const float*)d_in[0];
    const float* conv1_w = (const float*)d_in[1];
    const float* conv1_b = (const float*)d_in[2];
    const float* prim_w  = (const float*)d_in[3];
    const float* prim_b  = (const float*)d_in[4];
    const float* caps_w  = (const float*)d_in[5];
    const float* b_route = (const float*)d_in[6];
    const float* pred_w  = (const float*)d_in[7];
    const float* pred_b  = (const float*)d_in[8];
    const float* eos_w   = (const float*)d_in[9];
    const float* eos_b   = (const float*)d_in[10];
    float* out = (float*)d_out;

    u16 *inh, *inl, *w1h, *w1l, *w2h, *w2l, *c1h, *c1l;
    float *prim4, *upp, *bbp, *vp;
    cudaGetSymbolAddress((void**)&inh, g_inh);
    cudaGetSymbolAddress((void**)&inl, g_inl);
    cudaGetSymbolAddress((void**)&w1h, g_w1h);
    cudaGetSymbolAddress((void**)&w1l, g_w1l);
    cudaGetSymbolAddress((void**)&w2h, g_w2h);
    cudaGetSymbolAddress((void**)&w2l, g_w2l);
    cudaGetSymbolAddress((void**)&c1h, g_c1h);
    cudaGetSymbolAddress((void**)&c1l, g_c1l);
    cudaGetSymbolAddress((void**)&prim4, g_prim4);
    cudaGetSymbolAddress((void**)&upp, g_up);
    cudaGetSymbolAddress((void**)&bbp, g_bb);
    cudaGetSymbolAddress((void**)&vp, g_v);

    const int NBB = BATCH * NCAP * NCLS;
    const int NV = BATCH * NCLS * FD;

    prep_in<<<(BATCH * IH * PADW + 255) / 256, 256>>>(input, inh, inl);
    prep_c1w<<<(256 * K1 + 255) / 256, 256>>>(conv1_w, w1h, w1l);
    prep_c2w<<<(256 * K2 + 255) / 256, 256>>>(prim_w, w2h, w2l);
    conv1_mma<<<dim3(OH1, BATCH), 256>>>(inh, inl, w1h, w1l, conv1_b, c1h, c1l);
    conv2_mma<<<dim3(2, BATCH, KSPLIT), 256>>>(c1h, c1l, w2h, w2l, prim_b, prim4);
    squash_predict_kernel<<<dim3(NCAP, BATCH), 80>>>(prim4, caps_w, upp);
    route_s0_kernel<<<dim3(NCLS, BATCH), 256>>>(upp, b_route, vp);
    // it0: v0 -> v1, b_route -> bb0
    route_fused<<<dim3(NCLS, BATCH), 256>>>(upp, b_route, vp, vp + NV,
                                            bbp, bbp, 1);
    // it1: v1 -> v0, bb0 -> bb1
    route_fused<<<dim3(NCLS, BATCH), 256>>>(upp, b_route, vp + NV, vp,
                                            bbp, bbp + NBB, 0);
    // it2: v0 -> v1, bb1 -> bb0
    route_fused<<<dim3(NCLS, BATCH), 256>>>(upp, b_route, vp, vp + NV,
                                            bbp + NBB, bbp, 0);
    head_kernel<<<1, BATCH * NCLS>>>(vp + NV, pred_w, pred_b, eos_w, eos_b, out);
}

// round 7
// speedup vs baseline: 4.4936x; 1.4884x over previous
#include <cuda_runtime.h>
#include <cuda_fp16.h>
#include <math.h>
#include <stdint.h>

typedef unsigned short u16;

// ---------------- problem constants ----------------
#define BATCH 32
#define IH 120
#define IW 640
#define PADW 688          // padded input width (fp16 split arrays)
#define OH1 90            // only rows 0..89 consumed by conv2
#define NCAP 3456
#define NCLS 5
#define FD 16
#define JD 80
#define NREL 25
#define K1 4800
#define K2 25600
#define NPOS 108
#define KSPLIT 4

// ---------------- device scratch ----------------
__device__ u16 g_inh[(size_t)BATCH * IH * PADW];
__device__ u16 g_inl[(size_t)BATCH * IH * PADW];
__device__ u16 g_w1h[300 * 256 * 16];            // conv1 W hi [step][c][16]
__device__ u16 g_w2h[256 * K2];                  // conv2 W [c2][r*256+c1]
__device__ u16 g_w2l[256 * K2];
__device__ u16 g_c1h[(size_t)BATCH * NPOS * K2]; // conv1 out [b][pos][r*256+c]
__device__ u16 g_c1l[(size_t)BATCH * NPOS * K2];
__device__ float g_prim4[KSPLIT][BATCH * 256 * NPOS];
__device__ float g_up[BATCH * NCAP * JD];
__device__ float g_bb[2][BATCH * NCAP * NCLS];
__device__ float g_v[2][BATCH * NCLS * FD];

// ---------------- helpers ----------------
__device__ __forceinline__ void mma16816(float* c, const uint32_t* a,
                                         const uint32_t* b) {
    asm volatile(
        "mma.sync.aligned.m16n8k16.row.col.f32.f16.f16.f32 "
        "{%0,%1,%2,%3}, {%4,%5,%6,%7}, {%8,%9}, {%0,%1,%2,%3};"
        : "+f"(c[0]), "+f"(c[1]), "+f"(c[2]), "+f"(c[3])
        : "r"(a[0]), "r"(a[1]), "r"(a[2]), "r"(a[3]), "r"(b[0]), "r"(b[1]));
}
__device__ __forceinline__ void split16(float v, u16& h, u16& l) {
    __half hh = __float2half_rn(v);
    h = __half_as_ushort(hh);
    l = __half_as_ushort(__float2half_rn(v - __half2float(hh)));
}
__device__ __forceinline__ void cp16(uint32_t dst, const void* src) {
    asm volatile("cp.async.ca.shared.global [%0], [%1], 16;"
                 :: "r"(dst), "l"(src));
}
__device__ __forceinline__ void cp_commit() {
    asm volatile("cp.async.commit_group;");
}
__device__ __forceinline__ void cp_wait0() {
    asm volatile("cp.async.wait_group 0;");
}

// =====================================================================
// prep: split input to fp16 hi/lo, padded rows (cols 640..687 = 0)
// =====================================================================
__global__ void prep_in(const float* __restrict__ in, u16* __restrict__ ih,
                        u16* __restrict__ il) {
    int idx = blockIdx.x * 256 + threadIdx.x;
    if (idx >= BATCH * IH * PADW) return;
    int col = idx % PADW;
    int rb = idx / PADW;
    float v = (col < IW) ? in[(size_t)rb * IW + col] : 0.0f;
    split16(v, ih[idx], il[idx]);
}

// =====================================================================
// prep conv1 weights (hi only): (256,1,30,160) -> [step][c][16]
// =====================================================================
__global__ void prep_c1w(const float* __restrict__ w, u16* __restrict__ wh) {
    int idx = blockIdx.x * 256 + threadIdx.x;
    if (idx >= 256 * K1) return;
    int c = idx / K1;
    int k = idx - c * K1;
    int kh = k / 160, kw = k - kh * 160;
    int kws = kw >> 4, kk = kw & 15;
    wh[((kh * 10 + kws) * 256 + c) * 16 + kk] =
        __half_as_ushort(__float2half_rn(w[idx]));
}

// =====================================================================
// prep conv2 weights: (256,256,10,10) -> [c2][r*256+c1] hi/lo
// =====================================================================
__global__ void prep_c2w(const float* __restrict__ w2, u16* __restrict__ wh,
                         u16* __restrict__ wl) {
    int idx = blockIdx.x * 256 + threadIdx.x;
    if (idx >= 256 * K2) return;
    int c2 = idx / K2;
    int k = idx - c2 * K2;
    int r = k >> 8, c1 = k & 255;
    split16(w2[(size_t)(c2 * 256 + c1) * 100 + r], wh[idx], wl[idx]);
}

// =====================================================================
// conv1 via HMMA, 2-term split (A hi-only; B hi+lo).
// CTA = (mt, oh, b): tile M128 x N128(ow) x K4800, 2 CTAs/SM.
// 8 warps 2(M)x4(N), warp tile 64x32. A smem cp.async double-buffered,
// B fragments direct from pre-split gmem rows.
// =====================================================================
__global__ __launch_bounds__(256, 2)
void conv1_mma(const u16* __restrict__ inh, const u16* __restrict__ inl,
               const u16* __restrict__ w1h, const float* __restrict__ bias,
               u16* __restrict__ c1h, u16* __restrict__ c1l) {
    // [stage][128 rows x 8 u32], 16B halves XOR-swizzled by (row>>2)&1
    __shared__ uint32_t sA[2][1024];

    const int tid = threadIdx.x;
    const int wid = tid >> 5, lane = tid & 31;
    const int grp = lane >> 2, tig = lane & 3;
    const int wm = wid >> 2, wn = wid & 3;
    const int mt = blockIdx.x, oh = blockIdx.y, b = blockIdx.z;

    float acc[4][4][4] = {};

    // A staging: thread -> row tid>>1 (0..127), 16B chunk tid&1
    const int arow = tid >> 1, achk = tid & 1;
    const uint32_t sA0 = (uint32_t)__cvta_generic_to_shared(&sA[0][0]);
    const uint32_t adst_off = arow * 32 + ((achk ^ ((arow >> 2) & 1)) << 4);

    auto stageA = [&](int step, int stg) {
        const u16* src = w1h + ((size_t)step * 256 + mt * 128 + arow) * 16 + achk * 8;
        cp16(sA0 + stg * 4096 + adst_off, src);
        cp_commit();
    };

    stageA(0, 0);
    cp_wait0();
    __syncthreads();

    int kh = 0, kws = 0;
    for (int step = 0; step < 300; ++step) {
        const int stg = step & 1;
        if (step < 299) stageA(step + 1, stg ^ 1);

        // B fragments from pre-split gmem rows
        const u16* rh = inh + ((size_t)(b * IH + oh + kh)) * PADW + 16 * kws;
        const u16* rl = inl + ((size_t)(b * IH + oh + kh)) * PADW + 16 * kws;
        uint32_t bh[4][2], bl[4][2];
#pragma unroll
        for (int nf = 0; nf < 4; ++nf) {
            const int cb = 4 * (wn * 32 + nf * 8 + grp) + 2 * tig;
            bh[nf][0] = *(const uint32_t*)(rh + cb);
            bh[nf][1] = *(const uint32_t*)(rh + cb + 8);
            bl[nf][0] = *(const uint32_t*)(rl + cb);
            bl[nf][1] = *(const uint32_t*)(rl + cb + 8);
        }
        const uint32_t* A = sA[stg];
#pragma unroll
        for (int mf = 0; mf < 4; ++mf) {
            const int r0 = wm * 64 + mf * 16 + grp;
            const int sw = ((r0 >> 2) & 1) << 2;
            uint32_t a_h[4];
            a_h[0] = A[r0 * 8 + (0 ^ sw) + tig];
            a_h[1] = A[(r0 + 8) * 8 + (0 ^ sw) + tig];
            a_h[2] = A[r0 * 8 + (4 ^ sw) + tig];
            a_h[3] = A[(r0 + 8) * 8 + (4 ^ sw) + tig];
#pragma unroll
            for (int nf = 0; nf < 4; ++nf) {
                mma16816(acc[mf][nf], a_h, bh[nf]);
                mma16816(acc[mf][nf], a_h, bl[nf]);
            }
        }
        cp_wait0();
        __syncthreads();
        if (++kws == 10) { kws = 0; ++kh; }
    }

    // epilogue: bias + relu + fp16 split, conv2 im2col order
    const int ohh = oh / 10, kh2 = oh - 10 * ohh;
#pragma unroll
    for (int mf = 0; mf < 4; ++mf) {
#pragma unroll
        for (int nf = 0; nf < 4; ++nf) {
#pragma unroll
            for (int i = 0; i < 4; ++i) {
                const int c = mt * 128 + wm * 64 + mf * 16 + grp + (i >> 1) * 8;
                const int ow = wn * 32 + nf * 8 + 2 * tig + (i & 1);
                if (ow < 120) {
                    float v = fmaxf(acc[mf][nf][i] + bias[c], 0.0f);
                    int pos = ohh * 12 + ow / 10;
                    int r = kh2 * 10 + (ow % 10);
                    size_t o = (((size_t)b * NPOS + pos) * 100 + r) * 256 + c;
                    split16(v, c1h[o], c1l[o]);
                }
            }
        }
    }
}

// =====================================================================
// conv2 via HMMA (3-term): GEMM M=256 x N=108 x K=25600, 4-way K split.
// =====================================================================
__global__ __launch_bounds__(256, 2)
void conv2_mma(const u16* __restrict__ c1h, const u16* __restrict__ c1l,
               const u16* __restrict__ w2h, const u16* __restrict__ w2l,
               const float* __restrict__ pb, float* __restrict__ prim4) {
    __shared__ u16 s_Ah[128 * 16], s_Al[128 * 16];
    __shared__ u16 s_Bh[128 * 16], s_Bl[128 * 16];

    const int tid = threadIdx.x;
    const int wid = tid >> 5, lane = tid & 31;
    const int grp = lane >> 2, tig = lane & 3;
    const int msub = wid & 1, nsub = wid >> 1;
    const int mt = blockIdx.x, b = blockIdx.y, ks = blockIdx.z;

    float acc[4][4][4] = {};

    const int ar = tid >> 1, ah8 = (tid & 1) * 8;
    const u16* Ah = w2h + (size_t)(mt * 128 + ar) * K2 + ah8;
    const u16* Al = w2l + (size_t)(mt * 128 + ar) * K2 + ah8;
    const u16* Bh = c1h + ((size_t)b * NPOS + ar) * K2 + ah8;
    const u16* Bl = c1l + ((size_t)b * NPOS + ar) * K2 + ah8;
    const bool bvalid = ar < NPOS;

    const int kbase = ks * (K2 / KSPLIT);
    const int NSTEP = K2 / KSPLIT / 16;
    uint4 rAh = *(const uint4*)(Ah + kbase);
    uint4 rAl = *(const uint4*)(Al + kbase);
    uint4 z = make_uint4(0, 0, 0, 0);
    uint4 rBh = bvalid ? *(const uint4*)(Bh + kbase) : z;
    uint4 rBl = bvalid ? *(const uint4*)(Bl + kbase) : z;

    for (int s = 0; s < NSTEP; ++s) {
        __syncthreads();
        *(uint4*)(s_Ah + ar * 16 + ah8) = rAh;
        *(uint4*)(s_Al + ar * 16 + ah8) = rAl;
        *(uint4*)(s_Bh + ar * 16 + ah8) = rBh;
        *(uint4*)(s_Bl + ar * 16 + ah8) = rBl;
        __syncthreads();
        if (s < NSTEP - 1) {
            const int k = kbase + (s + 1) * 16;
            rAh = *(const uint4*)(Ah + k);
            rAl = *(const uint4*)(Al + k);
            rBh = bvalid ? *(const uint4*)(Bh + k) : z;
            rBl = bvalid ? *(const uint4*)(Bl + k) : z;
        }
        uint32_t bh[4][2], bl[4][2];
#pragma unroll
        for (int nf = 0; nf < 4; ++nf) {
            int n0 = (nsub * 32 + nf * 8 + grp) * 16 + 2 * tig;
            bh[nf][0] = *(const uint32_t*)(s_Bh + n0);
            bh[nf][1] = *(const uint32_t*)(s_Bh + n0 + 8);
            bl[nf][0] = *(const uint32_t*)(s_Bl + n0);
            bl[nf][1] = *(const uint32_t*)(s_Bl + n0 + 8);
        }
#pragma unroll
        for (int mf = 0; mf < 4; ++mf) {
            const int m0 = msub * 64 + mf * 16;
            uint32_t a_h[4], a_l[4];
            a_h[0] = *(const uint32_t*)(s_Ah + (m0 + grp) * 16 + 2 * tig);
            a_h[1] = *(const uint32_t*)(s_Ah + (m0 + grp + 8) * 16 + 2 * tig);
            a_h[2] = *(const uint32_t*)(s_Ah + (m0 + grp) * 16 + 2 * tig + 8);
            a_h[3] = *(const uint32_t*)(s_Ah + (m0 + grp + 8) * 16 + 2 * tig + 8);
            a_l[0] = *(const uint32_t*)(s_Al + (m0 + grp) * 16 + 2 * tig);
            a_l[1] = *(const uint32_t*)(s_Al + (m0 + grp + 8) * 16 + 2 * tig);
            a_l[2] = *(const uint32_t*)(s_Al + (m0 + grp) * 16 + 2 * tig + 8);
            a_l[3] = *(const uint32_t*)(s_Al + (m0 + grp + 8) * 16 + 2 * tig + 8);
#pragma unroll
            for (int nf = 0; nf < 4; ++nf) {
                mma16816(acc[mf][nf], a_h, bh[nf]);
                mma16816(acc[mf][nf], a_h, bl[nf]);
                mma16816(acc[mf][nf], a_l, bh[nf]);
            }
        }
    }

    float* outp = prim4 + (size_t)ks * (BATCH * 256 * NPOS);
#pragma unroll
    for (int mf = 0; mf < 4; ++mf) {
#pragma unroll
        for (int nf = 0; nf < 4; ++nf) {
#pragma unroll
            for (int i = 0; i < 4; ++i) {
                const int c2 = mt * 128 + msub * 64 + mf * 16 + grp + (i >> 1) * 8;
                const int n = nsub * 32 + nf * 8 + 2 * tig + (i & 1);
                if (n < NPOS) {
                    float v = acc[mf][nf][i] + (ks == 0 ? pb[c2] : 0.0f);
                    outp[((size_t)b * 256 + c2) * NPOS + n] = v;
                }
            }
        }
    }
}

// =====================================================================
// squash + caps prediction (sums 4 conv2 partials)
// =====================================================================
__global__ void squash_predict_kernel(const float* __restrict__ prim4,
                                      const float* __restrict__ caps_w,
                                      float* __restrict__ up) {
    __shared__ float su[8];
    __shared__ float sfac;
    const int i = blockIdx.x;
    const int b = blockIdx.y;
    const int g = i / NPOS;
    const int p = i - g * NPOS;
    const int t = threadIdx.x;
    const int SL = BATCH * 256 * NPOS;

    if (t < 8) {
        size_t o = ((size_t)b * 256 + g * 8 + t) * NPOS + p;
        su[t] = prim4[o] + prim4[o + SL] + prim4[o + 2 * SL] + prim4[o + 3 * SL];
    }
    __syncthreads();
    if (t == 0) {
        float l2 = 0.0f;
#pragma unroll
        for (int d = 0; d < 8; ++d) l2 += su[d] * su[d];
        sfac = sqrtf(l2) / (1.0f + l2);
    }
    __syncthreads();
    const float f = sfac;
    const float* cw = caps_w + (size_t)i * 8 * JD + t;
    float a = 0.0f;
#pragma unroll
    for (int d = 0; d < 8; ++d) a += su[d] * f * cw[d * JD];
    up[((size_t)b * NCAP + i) * JD + t] = a;
}

// =====================================================================
// routing iteration 0
// =====================================================================
__global__ void route_s0_kernel(const float* __restrict__ up,
                                const float* __restrict__ b_route,
                                float* __restrict__ vout) {
    const int o = blockIdx.x;
    const int b = blockIdx.y;
    const int t = threadIdx.x;
    const int lane = t & 31, wid = t >> 5;

    float sd[FD];
#pragma unroll
    for (int d = 0; d < FD; ++d) sd[d] = 0.0f;

    for (int i = t; i < NCAP; i += 256) {
        float br[NCLS];
#pragma unroll
        for (int oo = 0; oo < NCLS; ++oo) br[oo] = b_route[i * NCLS + oo];
        float m = br[0];
#pragma unroll
        for (int oo = 1; oo < NCLS; ++oo) m = fmaxf(m, br[oo]);
        float s = 0.0f;
#pragma unroll
        for (int oo = 0; oo < NCLS; ++oo) s += expf(br[oo] - m);
        float ci = expf(br[o] - m) / s;
        const float* u = up + ((size_t)b * NCAP + i) * JD + o * FD;
#pragma unroll
        for (int d = 0; d < FD; ++d) sd[d] += ci * u[d];
    }
#pragma unroll
    for (int d = 0; d < FD; ++d)
        for (int off = 16; off; off >>= 1)
            sd[d] += __shfl_down_sync(0xffffffffu, sd[d], off);

    __shared__ float part[8][FD];
    __shared__ float fin[FD];
    __shared__ float fac;
    if (lane == 0)
#pragma unroll
        for (int d = 0; d < FD; ++d) part[wid][d] = sd[d];
    __syncthreads();
    if (t < FD) {
        float tot = 0.0f;
#pragma unroll
        for (int ww = 0; ww < 8; ++ww) tot += part[ww][t];
        fin[t] = tot;
    }
    __syncthreads();
    if (t == 0) {
        float l2 = 0.0f;
#pragma unroll
        for (int d = 0; d < FD; ++d) l2 += fin[d] * fin[d];
        fac = sqrtf(l2) / (1.0f + l2);
    }
    __syncthreads();
    if (t < FD) vout[((size_t)b * NCLS + o) * FD + t] = fin[t] * fac;
}

// =====================================================================
// fused routing iteration (double-buffered bb and v)
// =====================================================================
__global__ void route_fused(const float* __restrict__ up,
                            const float* __restrict__ b_route,
                            const float* __restrict__ vin,
                            float* __restrict__ vout,
                            const float* __restrict__ bb_rd,
                            float* __restrict__ bb_wr, int first) {
    const int o = blockIdx.x;
    const int b = blockIdx.y;
    const int t = threadIdx.x;
    const int lane = t & 31, wid = t >> 5;

    __shared__ float sv[JD];
    if (t < JD) sv[t] = vin[b * JD + t];
    __syncthreads();

    float sd[FD];
#pragma unroll
    for (int d = 0; d < FD; ++d) sd[d] = 0.0f;

    for (int i = t; i < NCAP; i += 256) {
        const size_t base = ((size_t)b * NCAP + i);
        float u[JD];
        const float4* u4 = (const float4*)(up + base * JD);
#pragma unroll
        for (int q = 0; q < JD / 4; ++q) {
            float4 vv = u4[q];
            u[4 * q] = vv.x; u[4 * q + 1] = vv.y;
            u[4 * q + 2] = vv.z; u[4 * q + 3] = vv.w;
        }
        float nb[NCLS];
#pragma unroll
        for (int oo = 0; oo < NCLS; ++oo) {
            float dot = 0.0f;
#pragma unroll
            for (int d = 0; d < FD; ++d) dot += u[oo * FD + d] * sv[oo * FD + d];
            float prev = first ? b_route[i * NCLS + oo] : bb_rd[base * NCLS + oo];
            nb[oo] = prev + dot;
        }
        if (o == 0) {
#pragma unroll
            for (int oo = 0; oo < NCLS; ++oo) bb_wr[base * NCLS + oo] = nb[oo];
        }
        float m = nb[0];
#pragma unroll
        for (int oo = 1; oo < NCLS; ++oo) m = fmaxf(m, nb[oo]);
        float s = 0.0f;
#pragma unroll
        for (int oo = 0; oo < NCLS; ++oo) s += expf(nb[oo] - m);
        float ci = expf(nb[o] - m) / s;
#pragma unroll
        for (int d = 0; d < FD; ++d) sd[d] += ci * u[o * FD + d];
    }
#pragma unroll
    for (int d = 0; d < FD; ++d)
        for (int off = 16; off; off >>= 1)
            sd[d] += __shfl_down_sync(0xffffffffu, sd[d], off);

    __shared__ float part[8][FD];
    __shared__ float fin[FD];
    __shared__ float fac;
    if (lane == 0)
#pragma unroll
        for (int d = 0; d < FD; ++d) part[wid][d] = sd[d];
    __syncthreads();
    if (t < FD) {
        float tot = 0.0f;
#pragma unroll
        for (int ww = 0; ww < 8; ++ww) tot += part[ww][t];
        fin[t] = tot;
    }
    __syncthreads();
    if (t == 0) {
        float l2 = 0.0f;
#pragma unroll
        for (int d = 0; d < FD; ++d) l2 += fin[d] * fin[d];
        fac = sqrtf(l2) / (1.0f + l2);
    }
    __syncthreads();
    if (t < FD) vout[((size_t)b * NCLS + o) * FD + t] = fin[t] * fac;
}

// =====================================================================
// heads
// =====================================================================
__global__ void head_kernel(const float* __restrict__ v,
                            const float* __restrict__ pred_w,
                            const float* __restrict__ pred_b,
                            const float* __restrict__ eos_w,
                            const float* __restrict__ eos_b,
                            float* __restrict__ out) {
    const int t = threadIdx.x;
    if (t >= BATCH * NCLS) return;
    const float* vv = v + (size_t)t * FD;
    float lg[NREL + 1];
#pragma unroll 4
    for (int r = 0; r < NREL; ++r) {
        float a = pred_b[r];
#pragma unroll
        for (int d = 0; d < FD; ++d) a += vv[d] * pred_w[r * FD + d];
        lg[r] = a;
    }
    {
        float a = eos_b[0];
#pragma unroll
        for (int d = 0; d < FD; ++d) a += vv[d] * eos_w[d];
        lg[NREL] = a;
    }
    float m = lg[0];
#pragma unroll
    for (int k = 1; k <= NREL; ++k) m = fmaxf(m, lg[k]);
    float s = 0.0f;
#pragma unroll
    for (int k = 0; k <= NREL; ++k) s += expf(lg[k] - m);
    const float ls = m + logf(s);
#pragma unroll
    for (int k = 0; k <= NREL; ++k) out[(size_t)t * (NREL + 1) + k] = lg[k] - ls;
}

// =====================================================================
extern "C" void kernel_launch(void* const* d_in, const int* in_sizes, int n_in,
                              void* d_out, int out_size) {
    const float* input   = (const float*)d_in[0];
    const float* conv1_w = (const float*)d_in[1];
    const float* conv1_b = (const float*)d_in[2];
    const float* prim_w  = (const float*)d_in[3];
    const float* prim_b  = (const float*)d_in[4];
    const float* caps_w  = (const float*)d_in[5];
    const float* b_route = (const float*)d_in[6];
    const float* pred_w  = (const float*)d_in[7];
    const float* pred_b  = (const float*)d_in[8];
    const float* eos_w   = (const float*)d_in[9];
    const float* eos_b   = (const float*)d_in[10];
    float* out = (float*)d_out;

    u16 *inh, *inl, *w1h, *w2h, *w2l, *c1h, *c1l;
    float *prim4, *upp, *bbp, *vp;
    cudaGetSymbolAddress((void**)&inh, g_inh);
    cudaGetSymbolAddress((void**)&inl, g_inl);
    cudaGetSymbolAddress((void**)&w1h, g_w1h);
    cudaGetSymbolAddress((void**)&w2h, g_w2h);
    cudaGetSymbolAddress((void**)&w2l, g_w2l);
    cudaGetSymbolAddress((void**)&c1h, g_c1h);
    cudaGetSymbolAddress((void**)&c1l, g_c1l);
    cudaGetSymbolAddress((void**)&prim4, g_prim4);
    cudaGetSymbolAddress((void**)&upp, g_up);
    cudaGetSymbolAddress((void**)&bbp, g_bb);
    cudaGetSymbolAddress((void**)&vp, g_v);

    const int NBB = BATCH * NCAP * NCLS;
    const int NV = BATCH * NCLS * FD;

    prep_in<<<(BATCH * IH * PADW + 255) / 256, 256>>>(input, inh, inl);
    prep_c1w<<<(256 * K1 + 255) / 256, 256>>>(conv1_w, w1h);
    prep_c2w<<<(256 * K2 + 255) / 256, 256>>>(prim_w, w2h, w2l);
    conv1_mma<<<dim3(2, OH1, BATCH), 256>>>(inh, inl, w1h, conv1_b, c1h, c1l);
    conv2_mma<<<dim3(2, BATCH, KSPLIT), 256>>>(c1h, c1l, w2h, w2l, prim_b, prim4);
    squash_predict_kernel<<<dim3(NCAP, BATCH), 80>>>(prim4, caps_w, upp);
    route_s0_kernel<<<dim3(NCLS, BATCH), 256>>>(upp, b_route, vp);
    route_fused<<<dim3(NCLS, BATCH), 256>>>(upp, b_route, vp, vp + NV,
                                            bbp, bbp, 1);
    route_fused<<<dim3(NCLS, BATCH), 256>>>(upp, b_route, vp + NV, vp,
                                            bbp, bbp + NBB, 0);
    route_fused<<<dim3(NCLS, BATCH), 256>>>(upp, b_route, vp, vp + NV,
                                            bbp + NBB, bbp, 0);
    head_kernel<<<1, BATCH * NCLS>>>(vp + NV, pred_w, pred_b, eos_w, eos_b, out);
}

// round 8
// speedup vs baseline: 7.2853x; 1.6213x over previous
#include <cuda_runtime.h>
#include <cuda_fp16.h>
#include <math.h>
#include <stdint.h>

typedef unsigned short u16;

// ---------------- problem constants ----------------
#define BATCH 32
#define IH 120
#define IW 640
#define PADW 688          // padded input width (fp16)
#define OH1 90            // only rows 0..89 consumed by conv2
#define NCAP 3456
#define NCLS 5
#define FD 16
#define JD 80
#define NREL 25
#define K1 4800
#define K2 25600
#define NPOS 108
#define KSPLIT 4

// ---------------- device scratch ----------------
__device__ u16 g_in16[(size_t)BATCH * IH * PADW];
__device__ u16 g_w1h[300 * 256 * 16];            // conv1 W [step][c][16]
__device__ u16 g_w2h[256 * K2];                  // conv2 W [c2][r*256+c1]
__device__ u16 g_c1[(size_t)BATCH * NPOS * K2];  // conv1 out [b][pos][r*256+c]
__device__ float g_prim4[KSPLIT][BATCH * 256 * NPOS];
__device__ float g_up[BATCH * NCAP * JD];
__device__ float g_bb[2][BATCH * NCAP * NCLS];
__device__ float g_v[2][BATCH * NCLS * FD];

// ---------------- helpers ----------------
__device__ __forceinline__ void mma16816(float* c, const uint32_t* a,
                                         const uint32_t* b) {
    asm volatile(
        "mma.sync.aligned.m16n8k16.row.col.f32.f16.f16.f32 "
        "{%0,%1,%2,%3}, {%4,%5,%6,%7}, {%8,%9}, {%0,%1,%2,%3};"
        : "+f"(c[0]), "+f"(c[1]), "+f"(c[2]), "+f"(c[3])
        : "r"(a[0]), "r"(a[1]), "r"(a[2]), "r"(a[3]), "r"(b[0]), "r"(b[1]));
}
__device__ __forceinline__ void cp16(uint32_t dst, const void* src) {
    asm volatile("cp.async.ca.shared.global [%0], [%1], 16;"
                 :: "r"(dst), "l"(src));
}
__device__ __forceinline__ void cp_commit() {
    asm volatile("cp.async.commit_group;");
}
__device__ __forceinline__ void cp_wait0() {
    asm volatile("cp.async.wait_group 0;");
}

// =====================================================================
// prep: input -> fp16, padded rows (cols 640..687 = 0)
// =====================================================================
__global__ void prep_in(const float* __restrict__ in, u16* __restrict__ i16) {
    int idx = blockIdx.x * 256 + threadIdx.x;
    if (idx >= BATCH * IH * PADW) return;
    int col = idx % PADW;
    int rb = idx / PADW;
    float v = (col < IW) ? in[(size_t)rb * IW + col] : 0.0f;
    i16[idx] = __half_as_ushort(__float2half_rn(v));
}

// =====================================================================
// prep conv1 weights: (256,1,30,160) -> [step][c][16] fp16
// =====================================================================
__global__ void prep_c1w(const float* __restrict__ w, u16* __restrict__ wh) {
    int idx = blockIdx.x * 256 + threadIdx.x;
    if (idx >= 256 * K1) return;
    int c = idx / K1;
    int k = idx - c * K1;
    int kh = k / 160, kw = k - kh * 160;
    int kws = kw >> 4, kk = kw & 15;
    wh[((kh * 10 + kws) * 256 + c) * 16 + kk] =
        __half_as_ushort(__float2half_rn(w[idx]));
}

// =====================================================================
// prep conv2 weights: (256,256,10,10) -> [c2][r*256+c1] fp16
// =====================================================================
__global__ void prep_c2w(const float* __restrict__ w2, u16* __restrict__ wh) {
    int idx = blockIdx.x * 256 + threadIdx.x;
    if (idx >= 256 * K2) return;
    int c2 = idx / K2;
    int k = idx - c2 * K2;
    int r = k >> 8, c1 = k & 255;
    wh[idx] = __half_as_ushort(
        __float2half_rn(w2[(size_t)(c2 * 256 + c1) * 100 + r]));
}

// =====================================================================
// conv1 via HMMA, pure fp16. CTA = (mt, oh, b): M128 x N128(ow) x K4800.
// 8 warps 2(M)x4(N), warp tile 64x32. Two k16 slices per sync (k32/iter),
// A cp.async double-buffered, B fragments direct from fp16 gmem rows.
// =====================================================================
__global__ __launch_bounds__(256, 2)
void conv1_mma(const u16* __restrict__ in16, const u16* __restrict__ w1h,
               const float* __restrict__ bias, u16* __restrict__ c1) {
    // [stage][slice][128 rows x 8 u32], 16B halves swizzled by (row>>2)&1
    __shared__ uint32_t sA[2][2][1024];

    const int tid = threadIdx.x;
    const int wid = tid >> 5, lane = tid & 31;
    const int grp = lane >> 2, tig = lane & 3;
    const int wm = wid >> 2, wn = wid & 3;
    const int mt = blockIdx.x, oh = blockIdx.y, b = blockIdx.z;

    float acc[4][4][4] = {};

    const int arow = tid >> 1, achk = tid & 1;
    const uint32_t sA0 = (uint32_t)__cvta_generic_to_shared(&sA[0][0][0]);
    const uint32_t adst = arow * 32 + ((achk ^ ((arow >> 2) & 1)) << 4);

    // stage both k16 slices of iteration 'it' into buffer stg
    auto stageA = [&](int it, int stg) {
        const int step = (it / 5) * 10 + 2 * (it % 5);       // slice 0
        const u16* s0 = w1h + ((size_t)step * 256 + mt * 128 + arow) * 16 + achk * 8;
        cp16(sA0 + stg * 8192 + adst, s0);
        cp16(sA0 + stg * 8192 + 4096 + adst, s0 + 256 * 16); // slice 1 (step+1)
        cp_commit();
    };

    stageA(0, 0);
    cp_wait0();
    __syncthreads();

    for (int it = 0; it < 150; ++it) {
        const int stg = it & 1;
        if (it < 149) stageA(it + 1, stg ^ 1);

        const int kh = it / 5, kwp = it - 5 * kh;
        const u16* row = in16 + ((size_t)(b * IH + oh + kh)) * PADW + 32 * kwp;
        // B fragments for both slices straight from gmem
        uint32_t bf[2][4][2];
#pragma unroll
        for (int s2 = 0; s2 < 2; ++s2) {
            const u16* r = row + 16 * s2;
#pragma unroll
            for (int nf = 0; nf < 4; ++nf) {
                const int cb = 4 * (wn * 32 + nf * 8 + grp) + 2 * tig;
                bf[s2][nf][0] = *(const uint32_t*)(r + cb);
                bf[s2][nf][1] = *(const uint32_t*)(r + cb + 8);
            }
        }
#pragma unroll
        for (int mf = 0; mf < 4; ++mf) {
            const int r0 = wm * 64 + mf * 16 + grp;
            const int sw = ((r0 >> 2) & 1) << 2;
#pragma unroll
            for (int s2 = 0; s2 < 2; ++s2) {
                const uint32_t* A = sA[stg][s2];
                uint32_t a_h[4];
                a_h[0] = A[r0 * 8 + (0 ^ sw) + tig];
                a_h[1] = A[(r0 + 8) * 8 + (0 ^ sw) + tig];
                a_h[2] = A[r0 * 8 + (4 ^ sw) + tig];
                a_h[3] = A[(r0 + 8) * 8 + (4 ^ sw) + tig];
#pragma unroll
                for (int nf = 0; nf < 4; ++nf)
                    mma16816(acc[mf][nf], a_h, bf[s2][nf]);
            }
        }
        cp_wait0();
        __syncthreads();
    }

    // epilogue: bias + relu -> fp16, conv2 im2col order
    const int ohh = oh / 10, kh2 = oh - 10 * ohh;
#pragma unroll
    for (int mf = 0; mf < 4; ++mf) {
#pragma unroll
        for (int nf = 0; nf < 4; ++nf) {
#pragma unroll
            for (int i = 0; i < 4; ++i) {
                const int c = mt * 128 + wm * 64 + mf * 16 + grp + (i >> 1) * 8;
                const int ow = wn * 32 + nf * 8 + 2 * tig + (i & 1);
                if (ow < 120) {
                    float v = fmaxf(acc[mf][nf][i] + bias[c], 0.0f);
                    int pos = ohh * 12 + ow / 10;
                    int r = kh2 * 10 + (ow % 10);
                    c1[(((size_t)b * NPOS + pos) * 100 + r) * 256 + c] =
                        __half_as_ushort(__float2half_rn(v));
                }
            }
        }
    }
}

// =====================================================================
// conv2 via HMMA, pure fp16: GEMM M=256 x N=108 x K=25600, 4-way K split.
// =====================================================================
__global__ __launch_bounds__(256, 2)
void conv2_mma(const u16* __restrict__ c1, const u16* __restrict__ w2h,
               const float* __restrict__ pb, float* __restrict__ prim4) {
    __shared__ u16 s_A[128 * 16];
    __shared__ u16 s_B[128 * 16];

    const int tid = threadIdx.x;
    const int wid = tid >> 5, lane = tid & 31;
    const int grp = lane >> 2, tig = lane & 3;
    const int msub = wid & 1, nsub = wid >> 1;
    const int mt = blockIdx.x, b = blockIdx.y, ks = blockIdx.z;

    float acc[4][4][4] = {};

    const int ar = tid >> 1, ah8 = (tid & 1) * 8;
    const u16* Ap = w2h + (size_t)(mt * 128 + ar) * K2 + ah8;
    const u16* Bp = c1 + ((size_t)b * NPOS + ar) * K2 + ah8;
    const bool bvalid = ar < NPOS;

    const int kbase = ks * (K2 / KSPLIT);
    const int NSTEP = K2 / KSPLIT / 16;              // 400
    uint4 z = make_uint4(0, 0, 0, 0);
    uint4 rA = *(const uint4*)(Ap + kbase);
    uint4 rB = bvalid ? *(const uint4*)(Bp + kbase) : z;

    for (int s = 0; s < NSTEP; ++s) {
        __syncthreads();
        *(uint4*)(s_A + ar * 16 + ah8) = rA;
        *(uint4*)(s_B + ar * 16 + ah8) = rB;
        __syncthreads();
        if (s < NSTEP - 1) {
            const int k = kbase + (s + 1) * 16;
            rA = *(const uint4*)(Ap + k);
            rB = bvalid ? *(const uint4*)(Bp + k) : z;
        }
        uint32_t bf[4][2];
#pragma unroll
        for (int nf = 0; nf < 4; ++nf) {
            int n0 = (nsub * 32 + nf * 8 + grp) * 16 + 2 * tig;
            bf[nf][0] = *(const uint32_t*)(s_B + n0);
            bf[nf][1] = *(const uint32_t*)(s_B + n0 + 8);
        }
#pragma unroll
        for (int mf = 0; mf < 4; ++mf) {
            const int m0 = msub * 64 + mf * 16;
            uint32_t a_h[4];
            a_h[0] = *(const uint32_t*)(s_A + (m0 + grp) * 16 + 2 * tig);
            a_h[1] = *(const uint32_t*)(s_A + (m0 + grp + 8) * 16 + 2 * tig);
            a_h[2] = *(const uint32_t*)(s_A + (m0 + grp) * 16 + 2 * tig + 8);
            a_h[3] = *(const uint32_t*)(s_A + (m0 + grp + 8) * 16 + 2 * tig + 8);
#pragma unroll
            for (int nf = 0; nf < 4; ++nf)
                mma16816(acc[mf][nf], a_h, bf[nf]);
        }
    }

    float* outp = prim4 + (size_t)ks * (BATCH * 256 * NPOS);
#pragma unroll
    for (int mf = 0; mf < 4; ++mf) {
#pragma unroll
        for (int nf = 0; nf < 4; ++nf) {
#pragma unroll
            for (int i = 0; i < 4; ++i) {
                const int c2 = mt * 128 + msub * 64 + mf * 16 + grp + (i >> 1) * 8;
                const int n = nsub * 32 + nf * 8 + 2 * tig + (i & 1);
                if (n < NPOS) {
                    float v = acc[mf][nf][i] + (ks == 0 ? pb[c2] : 0.0f);
                    outp[((size_t)b * 256 + c2) * NPOS + n] = v;
                }
            }
        }
    }
}

// =====================================================================
// squash + caps prediction (sums 4 conv2 partials)
// =====================================================================
__global__ void squash_predict_kernel(const float* __restrict__ prim4,
                                      const float* __restrict__ caps_w,
                                      float* __restrict__ up) {
    __shared__ float su[8];
    __shared__ float sfac;
    const int i = blockIdx.x;
    const int b = blockIdx.y;
    const int g = i / NPOS;
    const int p = i - g * NPOS;
    const int t = threadIdx.x;
    const int SL = BATCH * 256 * NPOS;

    if (t < 8) {
        size_t o = ((size_t)b * 256 + g * 8 + t) * NPOS + p;
        su[t] = prim4[o] + prim4[o + SL] + prim4[o + 2 * SL] + prim4[o + 3 * SL];
    }
    __syncthreads();
    if (t == 0) {
        float l2 = 0.0f;
#pragma unroll
        for (int d = 0; d < 8; ++d) l2 += su[d] * su[d];
        sfac = sqrtf(l2) / (1.0f + l2);
    }
    __syncthreads();
    const float f = sfac;
    const float* cw = caps_w + (size_t)i * 8 * JD + t;
    float a = 0.0f;
#pragma unroll
    for (int d = 0; d < 8; ++d) a += su[d] * f * cw[d * JD];
    up[((size_t)b * NCAP + i) * JD + t] = a;
}

// =====================================================================
// routing iteration 0
// =====================================================================
__global__ void route_s0_kernel(const float* __restrict__ up,
                                const float* __restrict__ b_route,
                                float* __restrict__ vout) {
    const int o = blockIdx.x;
    const int b = blockIdx.y;
    const int t = threadIdx.x;
    const int lane = t & 31, wid = t >> 5;

    float sd[FD];
#pragma unroll
    for (int d = 0; d < FD; ++d) sd[d] = 0.0f;

    for (int i = t; i < NCAP; i += 256) {
        float br[NCLS];
#pragma unroll
        for (int oo = 0; oo < NCLS; ++oo) br[oo] = b_route[i * NCLS + oo];
        float m = br[0];
#pragma unroll
        for (int oo = 1; oo < NCLS; ++oo) m = fmaxf(m, br[oo]);
        float s = 0.0f;
#pragma unroll
        for (int oo = 0; oo < NCLS; ++oo) s += expf(br[oo] - m);
        float ci = expf(br[o] - m) / s;
        const float* u = up + ((size_t)b * NCAP + i) * JD + o * FD;
#pragma unroll
        for (int d = 0; d < FD; ++d) sd[d] += ci * u[d];
    }
#pragma unroll
    for (int d = 0; d < FD; ++d)
        for (int off = 16; off; off >>= 1)
            sd[d] += __shfl_down_sync(0xffffffffu, sd[d], off);

    __shared__ float part[8][FD];
    __shared__ float fin[FD];
    __shared__ float fac;
    if (lane == 0)
#pragma unroll
        for (int d = 0; d < FD; ++d) part[wid][d] = sd[d];
    __syncthreads();
    if (t < FD) {
        float tot = 0.0f;
#pragma unroll
        for (int ww = 0; ww < 8; ++ww) tot += part[ww][t];
        fin[t] = tot;
    }
    __syncthreads();
    if (t == 0) {
        float l2 = 0.0f;
#pragma unroll
        for (int d = 0; d < FD; ++d) l2 += fin[d] * fin[d];
        fac = sqrtf(l2) / (1.0f + l2);
    }
    __syncthreads();
    if (t < FD) vout[((size_t)b * NCLS + o) * FD + t] = fin[t] * fac;
}

// =====================================================================
// fused routing iteration (double-buffered bb and v)
// =====================================================================
__global__ void route_fused(const float* __restrict__ up,
                            const float* __restrict__ b_route,
                            const float* __restrict__ vin,
                            float* __restrict__ vout,
                            const float* __restrict__ bb_rd,
                            float* __restrict__ bb_wr, int first) {
    const int o = blockIdx.x;
    const int b = blockIdx.y;
    const int t = threadIdx.x;
    const int lane = t & 31, wid = t >> 5;

    __shared__ float sv[JD];
    if (t < JD) sv[t] = vin[b * JD + t];
    __syncthreads();

    float sd[FD];
#pragma unroll
    for (int d = 0; d < FD; ++d) sd[d] = 0.0f;

    for (int i = t; i < NCAP; i += 256) {
        const size_t base = ((size_t)b * NCAP + i);
        float u[JD];
        const float4* u4 = (const float4*)(up + base * JD);
#pragma unroll
        for (int q = 0; q < JD / 4; ++q) {
            float4 vv = u4[q];
            u[4 * q] = vv.x; u[4 * q + 1] = vv.y;
            u[4 * q + 2] = vv.z; u[4 * q + 3] = vv.w;
        }
        float nb[NCLS];
#pragma unroll
        for (int oo = 0; oo < NCLS; ++oo) {
            float dot = 0.0f;
#pragma unroll
            for (int d = 0; d < FD; ++d) dot += u[oo * FD + d] * sv[oo * FD + d];
            float prev = first ? b_route[i * NCLS + oo] : bb_rd[base * NCLS + oo];
            nb[oo] = prev + dot;
        }
        if (o == 0) {
#pragma unroll
            for (int oo = 0; oo < NCLS; ++oo) bb_wr[base * NCLS + oo] = nb[oo];
        }
        float m = nb[0];
#pragma unroll
        for (int oo = 1; oo < NCLS; ++oo) m = fmaxf(m, nb[oo]);
        float s = 0.0f;
#pragma unroll
        for (int oo = 0; oo < NCLS; ++oo) s += expf(nb[oo] - m);
        float ci = expf(nb[o] - m) / s;
#pragma unroll
        for (int d = 0; d < FD; ++d) sd[d] += ci * u[o * FD + d];
    }
#pragma unroll
    for (int d = 0; d < FD; ++d)
        for (int off = 16; off; off >>= 1)
            sd[d] += __shfl_down_sync(0xffffffffu, sd[d], off);

    __shared__ float part[8][FD];
    __shared__ float fin[FD];
    __shared__ float fac;
    if (lane == 0)
#pragma unroll
        for (int d = 0; d < FD; ++d) part[wid][d] = sd[d];
    __syncthreads();
    if (t < FD) {
        float tot = 0.0f;
#pragma unroll
        for (int ww = 0; ww < 8; ++ww) tot += part[ww][t];
        fin[t] = tot;
    }
    __syncthreads();
    if (t == 0) {
        float l2 = 0.0f;
#pragma unroll
        for (int d = 0; d < FD; ++d) l2 += fin[d] * fin[d];
        fac = sqrtf(l2) / (1.0f + l2);
    }
    __syncthreads();
    if (t < FD) vout[((size_t)b * NCLS + o) * FD + t] = fin[t] * fac;
}

// =====================================================================
// heads
// =====================================================================
__global__ void head_kernel(const float* __restrict__ v,
                            const float* __restrict__ pred_w,
                            const float* __restrict__ pred_b,
                            const float* __restrict__ eos_w,
                            const float* __restrict__ eos_b,
                            float* __restrict__ out) {
    const int t = threadIdx.x;
    if (t >= BATCH * NCLS) return;
    const float* vv = v + (size_t)t * FD;
    float lg[NREL + 1];
#pragma unroll 4
    for (int r = 0; r < NREL; ++r) {
        float a = pred_b[r];
#pragma unroll
        for (int d = 0; d < FD; ++d) a += vv[d] * pred_w[r * FD + d];
        lg[r] = a;
    }
    {
        float a = eos_b[0];
#pragma unroll
        for (int d = 0; d < FD; ++d) a += vv[d] * eos_w[d];
        lg[NREL] = a;
    }
    float m = lg[0];
#pragma unroll
    for (int k = 1; k <= NREL; ++k) m = fmaxf(m, lg[k]);
    float s = 0.0f;
#pragma unroll
    for (int k = 0; k <= NREL; ++k) s += expf(lg[k] - m);
    const float ls = m + logf(s);
#pragma unroll
    for (int k = 0; k <= NREL; ++k) out[(size_t)t * (NREL + 1) + k] = lg[k] - ls;
}

// =====================================================================
extern "C" void kernel_launch(void* const* d_in, const int* in_sizes, int n_in,
                              void* d_out, int out_size) {
    const float* input   = (const float*)d_in[0];
    const float* conv1_w = (const float*)d_in[1];
    const float* conv1_b = (const float*)d_in[2];
    const float* prim_w  = (const float*)d_in[3];
    const float* prim_b  = (const float*)d_in[4];
    const float* caps_w  = (const float*)d_in[5];
    const float* b_route = (const float*)d_in[6];
    const float* pred_w  = (const float*)d_in[7];
    const float* pred_b  = (const float*)d_in[8];
    const float* eos_w   = (const float*)d_in[9];
    const float* eos_b   = (const float*)d_in[10];
    float* out = (float*)d_out;

    u16 *in16, *w1h, *w2h, *c1;
    float *prim4, *upp, *bbp, *vp;
    cudaGetSymbolAddress((void**)&in16, g_in16);
    cudaGetSymbolAddress((void**)&w1h, g_w1h);
    cudaGetSymbolAddress((void**)&w2h, g_w2h);
    cudaGetSymbolAddress((void**)&c1, g_c1);
    cudaGetSymbolAddress((void**)&prim4, g_prim4);
    cudaGetSymbolAddress((void**)&upp, g_up);
    cudaGetSymbolAddress((void**)&bbp, g_bb);
    cudaGetSymbolAddress((void**)&vp, g_v);

    const int NBB = BATCH * NCAP * NCLS;
    const int NV = BATCH * NCLS * FD;

    prep_in<<<(BATCH * IH * PADW + 255) / 256, 256>>>(input, in16);
    prep_c1w<<<(256 * K1 + 255) / 256, 256>>>(conv1_w, w1h);
    prep_c2w<<<(256 * K2 + 255) / 256, 256>>>(prim_w, w2h);
    conv1_mma<<<dim3(2, OH1, BATCH), 256>>>(in16, w1h, conv1_b, c1);
    conv2_mma<<<dim3(2, BATCH, KSPLIT), 256>>>(c1, w2h, prim_b, prim4);
    squash_predict_kernel<<<dim3(NCAP, BATCH), 80>>>(prim4, caps_w, upp);
    route_s0_kernel<<<dim3(NCLS, BATCH), 256>>>(upp, b_route, vp);
    route_fused<<<dim3(NCLS, BATCH), 256>>>(upp, b_route, vp, vp + NV,
                                            bbp, bbp, 1);
    route_fused<<<dim3(NCLS, BATCH), 256>>>(upp, b_route, vp + NV, vp,
                                            bbp, bbp + NBB, 0);
    route_fused<<<dim3(NCLS, BATCH), 256>>>(upp, b_route, vp, vp + NV,
                                            bbp + NBB, bbp, 0);
    head_kernel<<<1, BATCH * NCLS>>>(vp + NV, pred_w, pred_b, eos_w, eos_b, out);
}

// round 9
// speedup vs baseline: 8.2811x; 1.1367x over previous
#include <cuda_runtime.h>
#include <cuda_fp16.h>
#include <math.h>
#include <stdint.h>

typedef unsigned short u16;

// ---------------- problem constants ----------------
#define BATCH 32
#define IH 120
#define IW 640
#define OH1 90            // only rows 0..89 consumed by conv2
#define NCAP 3456
#define NCLS 5
#define FD 16
#define JD 80
#define NREL 25
#define K1 4800
#define K2 25600
#define NPOS 108
#define KSPLIT 4

// ---------------- device scratch ----------------
// B operand, fragment order: [(b*120+row)*10+slice][j 0..15][lane][2 u32]
__device__ uint32_t g_inf[(size_t)BATCH * IH * 10 * 1024];
// A operand, fragment order: [step*16+rb][lane][4 u32]
__device__ uint4 g_w1f[300 * 16 * 32];
__device__ u16 g_w2h[256 * K2];                  // conv2 W [c2][r*256+c1]
__device__ u16 g_c1[(size_t)BATCH * NPOS * K2];  // conv1 out [b][pos][r*256+c]
__device__ float g_prim4[KSPLIT][BATCH * 256 * NPOS];
__device__ float g_up[BATCH * NCAP * JD];
__device__ float g_bb[2][BATCH * NCAP * NCLS];
__device__ float g_v[2][BATCH * NCLS * FD];

// ---------------- helpers ----------------
__device__ __forceinline__ void mma16816(float* c, const uint32_t* a,
                                         const uint32_t* b) {
    asm volatile(
        "mma.sync.aligned.m16n8k16.row.col.f32.f16.f16.f32 "
        "{%0,%1,%2,%3}, {%4,%5,%6,%7}, {%8,%9}, {%0,%1,%2,%3};"
        : "+f"(c[0]), "+f"(c[1]), "+f"(c[2]), "+f"(c[3])
        : "r"(a[0]), "r"(a[1]), "r"(a[2]), "r"(a[3]), "r"(b[0]), "r"(b[1]));
}
__device__ __forceinline__ void cp16(uint32_t dst, const void* src) {
    asm volatile("cp.async.ca.shared.global [%0], [%1], 16;"
                 :: "r"(dst), "l"(src));
}
__device__ __forceinline__ void cp_commit() {
    asm volatile("cp.async.commit_group;");
}
__device__ __forceinline__ void cp_wait0() {
    asm volatile("cp.async.wait_group 0;");
}
__device__ __forceinline__ uint32_t pack2h(float v0, float v1) {
    __half2 h = __floats2half2_rn(v0, v1);
    return *(uint32_t*)&h;
}

// =====================================================================
// prep: input -> B fragment order.
// col0 = 4*(8*j+grp) + 16*sg + 2*tig + 8*w ; zero beyond width.
// =====================================================================
__global__ void prep_inf(const float* __restrict__ in,
                         uint32_t* __restrict__ inf) {
    size_t idx = (size_t)blockIdx.x * 256 + threadIdx.x;
    if (idx >= (size_t)BATCH * IH * 10 * 1024) return;
    int w = idx & 1;
    int lane = (idx >> 1) & 31;
    int j = (idx >> 6) & 15;
    size_t t = idx >> 10;
    int sg = (int)(t % 10);
    size_t rowb = t / 10;                  // b*IH + row
    int grp = lane >> 2, tig = lane & 3;
    int col0 = 4 * (8 * j + grp) + 16 * sg + 2 * tig + 8 * w;
    float v0 = (col0 < IW) ? in[rowb * IW + col0] : 0.0f;
    float v1 = (col0 + 1 < IW) ? in[rowb * IW + col0 + 1] : 0.0f;
    inf[idx] = pack2h(v0, v1);
}

// =====================================================================
// prep conv1 weights -> A fragment order.
// j: bit0 -> row+8, bit1 -> k+8.
// =====================================================================
__global__ void prep_c1wf(const float* __restrict__ w,
                          uint32_t* __restrict__ w1f) {
    int idx = blockIdx.x * 256 + threadIdx.x;   // u32 index, 614400 total
    if (idx >= 300 * 16 * 32 * 4) return;
    int j = idx & 3;
    int lane = (idx >> 2) & 31;
    int rb = (idx >> 7) & 15;
    int step = idx >> 11;
    int grp = lane >> 2, tig = lane & 3;
    int c = rb * 16 + grp + (j & 1) * 8;
    int kk = 2 * tig + (j >> 1) * 8;
    int kh = step / 10, kws = step - 10 * kh;
    int kg = kh * 160 + kws * 16 + kk;
    w1f[idx] = pack2h(w[(size_t)c * K1 + kg], w[(size_t)c * K1 + kg + 1]);
}

// =====================================================================
// prep conv2 weights: (256,256,10,10) -> [c2][r*256+c1] fp16
// =====================================================================
__global__ void prep_c2w(const float* __restrict__ w2, u16* __restrict__ wh) {
    int idx = blockIdx.x * 256 + threadIdx.x;
    if (idx >= 256 * K2) return;
    int c2 = idx / K2;
    int k = idx - c2 * K2;
    int r = k >> 8, c1 = k & 255;
    wh[idx] = __half_as_ushort(
        __float2half_rn(w2[(size_t)(c2 * 256 + c1) * 100 + r]));
}

// =====================================================================
// conv1 via HMMA, pure fp16, fragment-order operands.
// CTA = (mt, oh, b): M128 x N128(ow) x K4800, 5 k16-slices per sync
// (60 iters). A: cp.async double-buffered smem, LDS.128 fragments.
// B: LDG.64 fragments direct from fragment-order gmem.
// =====================================================================
__global__ __launch_bounds__(256, 2)
void conv1_mma(const uint32_t* __restrict__ inf, const uint4* __restrict__ w1f,
               const float* __restrict__ bias, u16* __restrict__ c1) {
    __shared__ uint4 sA[2][1280];   // [stage][slice*256 + rb*32 + lane] 20KB ea

    const int tid = threadIdx.x;
    const int wid = tid >> 5, lane = tid & 31;
    const int grp = lane >> 2, tig = lane & 3;
    const int wm = wid >> 2, wn = wid & 3;
    const int mt = blockIdx.x, oh = blockIdx.y, b = blockIdx.z;

    float acc[4][4][4] = {};

    const uint32_t sA0 = (uint32_t)__cvta_generic_to_shared(&sA[0][0]);

    auto stageA = [&](int it, int stg) {
#pragma unroll
        for (int r = 0; r < 5; ++r) {
            const int c = tid + (r << 8);              // 0..1279
            const int slice = c >> 8;
            const int rbl = (c >> 5) & 7;
            const int ln = c & 31;
            const int step = it * 5 + slice;
            cp16(sA0 + stg * 20480 + c * 16,
                 w1f + ((step * 16 + mt * 8 + rbl) * 32 + ln));
        }
        cp_commit();
    };

    stageA(0, 0);
    cp_wait0();
    __syncthreads();

    for (int it = 0; it < 60; ++it) {
        const int stg = it & 1;
        if (it < 59) stageA(it + 1, stg ^ 1);

        const size_t rowb = (size_t)b * IH + oh + (it >> 1);
        const uint32_t* bb = inf + (rowb * 10 + 5 * (it & 1)) * 1024 +
                             wn * 256 + lane * 2;
#pragma unroll
        for (int s = 0; s < 5; ++s) {
            uint2 bf[4];
#pragma unroll
            for (int nf = 0; nf < 4; ++nf)
                bf[nf] = *(const uint2*)(bb + s * 1024 + nf * 64);
            uint4 af[4];
#pragma unroll
            for (int mf = 0; mf < 4; ++mf)
                af[mf] = sA[stg][s * 256 + (wm * 4 + mf) * 32 + lane];
#pragma unroll
            for (int mf = 0; mf < 4; ++mf)
#pragma unroll
                for (int nf = 0; nf < 4; ++nf)
                    mma16816(acc[mf][nf], (const uint32_t*)&af[mf],
                             (const uint32_t*)&bf[nf]);
        }
        cp_wait0();
        __syncthreads();
    }

    // epilogue: bias + relu -> fp16, conv2 im2col order
    const int ohh = oh / 10, kh2 = oh - 10 * ohh;
#pragma unroll
    for (int mf = 0; mf < 4; ++mf) {
#pragma unroll
        for (int nf = 0; nf < 4; ++nf) {
#pragma unroll
            for (int i = 0; i < 4; ++i) {
                const int c = mt * 128 + wm * 64 + mf * 16 + grp + (i >> 1) * 8;
                const int ow = wn * 32 + nf * 8 + 2 * tig + (i & 1);
                if (ow < 120) {
                    float v = fmaxf(acc[mf][nf][i] + bias[c], 0.0f);
                    int pos = ohh * 12 + ow / 10;
                    int r = kh2 * 10 + (ow % 10);
                    c1[(((size_t)b * NPOS + pos) * 100 + r) * 256 + c] =
                        __half_as_ushort(__float2half_rn(v));
                }
            }
        }
    }
}

// =====================================================================
// conv2 via HMMA, pure fp16: GEMM M=256 x N=108 x K=25600, 4-way K split.
// =====================================================================
__global__ __launch_bounds__(256, 2)
void conv2_mma(const u16* __restrict__ c1, const u16* __restrict__ w2h,
               const float* __restrict__ pb, float* __restrict__ prim4) {
    __shared__ u16 s_A[128 * 16];
    __shared__ u16 s_B[128 * 16];

    const int tid = threadIdx.x;
    const int wid = tid >> 5, lane = tid & 31;
    const int grp = lane >> 2, tig = lane & 3;
    const int msub = wid & 1, nsub = wid >> 1;
    const int mt = blockIdx.x, b = blockIdx.y, ks = blockIdx.z;

    float acc[4][4][4] = {};

    const int ar = tid >> 1, ah8 = (tid & 1) * 8;
    const u16* Ap = w2h + (size_t)(mt * 128 + ar) * K2 + ah8;
    const u16* Bp = c1 + ((size_t)b * NPOS + ar) * K2 + ah8;
    const bool bvalid = ar < NPOS;

    const int kbase = ks * (K2 / KSPLIT);
    const int NSTEP = K2 / KSPLIT / 16;              // 400
    uint4 z = make_uint4(0, 0, 0, 0);
    uint4 rA = *(const uint4*)(Ap + kbase);
    uint4 rB = bvalid ? *(const uint4*)(Bp + kbase) : z;

    for (int s = 0; s < NSTEP; ++s) {
        __syncthreads();
        *(uint4*)(s_A + ar * 16 + ah8) = rA;
        *(uint4*)(s_B + ar * 16 + ah8) = rB;
        __syncthreads();
        if (s < NSTEP - 1) {
            const int k = kbase + (s + 1) * 16;
            rA = *(const uint4*)(Ap + k);
            rB = bvalid ? *(const uint4*)(Bp + k) : z;
        }
        uint32_t bf[4][2];
#pragma unroll
        for (int nf = 0; nf < 4; ++nf) {
            int n0 = (nsub * 32 + nf * 8 + grp) * 16 + 2 * tig;
            bf[nf][0] = *(const uint32_t*)(s_B + n0);
            bf[nf][1] = *(const uint32_t*)(s_B + n0 + 8);
        }
#pragma unroll
        for (int mf = 0; mf < 4; ++mf) {
            const int m0 = msub * 64 + mf * 16;
            uint32_t a_h[4];
            a_h[0] = *(const uint32_t*)(s_A + (m0 + grp) * 16 + 2 * tig);
            a_h[1] = *(const uint32_t*)(s_A + (m0 + grp + 8) * 16 + 2 * tig);
            a_h[2] = *(const uint32_t*)(s_A + (m0 + grp) * 16 + 2 * tig + 8);
            a_h[3] = *(const uint32_t*)(s_A + (m0 + grp + 8) * 16 + 2 * tig + 8);
#pragma unroll
            for (int nf = 0; nf < 4; ++nf)
                mma16816(acc[mf][nf], a_h, bf[nf]);
        }
    }

    float* outp = prim4 + (size_t)ks * (BATCH * 256 * NPOS);
#pragma unroll
    for (int mf = 0; mf < 4; ++mf) {
#pragma unroll
        for (int nf = 0; nf < 4; ++nf) {
#pragma unroll
            for (int i = 0; i < 4; ++i) {
                const int c2 = mt * 128 + msub * 64 + mf * 16 + grp + (i >> 1) * 8;
                const int n = nsub * 32 + nf * 8 + 2 * tig + (i & 1);
                if (n < NPOS) {
                    float v = acc[mf][nf][i] + (ks == 0 ? pb[c2] : 0.0f);
                    outp[((size_t)b * 256 + c2) * NPOS + n] = v;
                }
            }
        }
    }
}

// =====================================================================
// squash + caps prediction (sums 4 conv2 partials)
// =====================================================================
__global__ void squash_predict_kernel(const float* __restrict__ prim4,
                                      const float* __restrict__ caps_w,
                                      float* __restrict__ up) {
    __shared__ float su[8];
    __shared__ float sfac;
    const int i = blockIdx.x;
    const int b = blockIdx.y;
    const int g = i / NPOS;
    const int p = i - g * NPOS;
    const int t = threadIdx.x;
    const int SL = BATCH * 256 * NPOS;

    if (t < 8) {
        size_t o = ((size_t)b * 256 + g * 8 + t) * NPOS + p;
        su[t] = prim4[o] + prim4[o + SL] + prim4[o + 2 * SL] + prim4[o + 3 * SL];
    }
    __syncthreads();
    if (t == 0) {
        float l2 = 0.0f;
#pragma unroll
        for (int d = 0; d < 8; ++d) l2 += su[d] * su[d];
        sfac = sqrtf(l2) / (1.0f + l2);
    }
    __syncthreads();
    const float f = sfac;
    const float* cw = caps_w + (size_t)i * 8 * JD + t;
    float a = 0.0f;
#pragma unroll
    for (int d = 0; d < 8; ++d) a += su[d] * f * cw[d * JD];
    up[((size_t)b * NCAP + i) * JD + t] = a;
}

// =====================================================================
// routing iteration 0
// =====================================================================
__global__ void route_s0_kernel(const float* __restrict__ up,
                                const float* __restrict__ b_route,
                                float* __restrict__ vout) {
    const int o = blockIdx.x;
    const int b = blockIdx.y;
    const int t = threadIdx.x;
    const int lane = t & 31, wid = t >> 5;

    float sd[FD];
#pragma unroll
    for (int d = 0; d < FD; ++d) sd[d] = 0.0f;

    for (int i = t; i < NCAP; i += 256) {
        float br[NCLS];
#pragma unroll
        for (int oo = 0; oo < NCLS; ++oo) br[oo] = b_route[i * NCLS + oo];
        float m = br[0];
#pragma unroll
        for (int oo = 1; oo < NCLS; ++oo) m = fmaxf(m, br[oo]);
        float s = 0.0f;
#pragma unroll
        for (int oo = 0; oo < NCLS; ++oo) s += expf(br[oo] - m);
        float ci = expf(br[o] - m) / s;
        const float* u = up + ((size_t)b * NCAP + i) * JD + o * FD;
#pragma unroll
        for (int d = 0; d < FD; ++d) sd[d] += ci * u[d];
    }
#pragma unroll
    for (int d = 0; d < FD; ++d)
        for (int off = 16; off; off >>= 1)
            sd[d] += __shfl_down_sync(0xffffffffu, sd[d], off);

    __shared__ float part[8][FD];
    __shared__ float fin[FD];
    __shared__ float fac;
    if (lane == 0)
#pragma unroll
        for (int d = 0; d < FD; ++d) part[wid][d] = sd[d];
    __syncthreads();
    if (t < FD) {
        float tot = 0.0f;
#pragma unroll
        for (int ww = 0; ww < 8; ++ww) tot += part[ww][t];
        fin[t] = tot;
    }
    __syncthreads();
    if (t == 0) {
        float l2 = 0.0f;
#pragma unroll
        for (int d = 0; d < FD; ++d) l2 += fin[d] * fin[d];
        fac = sqrtf(l2) / (1.0f + l2);
    }
    __syncthreads();
    if (t < FD) vout[((size_t)b * NCLS + o) * FD + t] = fin[t] * fac;
}

// =====================================================================
// fused routing iteration (double-buffered bb and v)
// =====================================================================
__global__ void route_fused(const float* __restrict__ up,
                            const float* __restrict__ b_route,
                            const float* __restrict__ vin,
                            float* __restrict__ vout,
                            const float* __restrict__ bb_rd,
                            float* __restrict__ bb_wr, int first) {
    const int o = blockIdx.x;
    const int b = blockIdx.y;
    const int t = threadIdx.x;
    const int lane = t & 31, wid = t >> 5;

    __shared__ float sv[JD];
    if (t < JD) sv[t] = vin[b * JD + t];
    __syncthreads();

    float sd[FD];
#pragma unroll
    for (int d = 0; d < FD; ++d) sd[d] = 0.0f;

    for (int i = t; i < NCAP; i += 256) {
        const size_t base = ((size_t)b * NCAP + i);
        float u[JD];
        const float4* u4 = (const float4*)(up + base * JD);
#pragma unroll
        for (int q = 0; q < JD / 4; ++q) {
            float4 vv = u4[q];
            u[4 * q] = vv.x; u[4 * q + 1] = vv.y;
            u[4 * q + 2] = vv.z; u[4 * q + 3] = vv.w;
        }
        float nb[NCLS];
#pragma unroll
        for (int oo = 0; oo < NCLS; ++oo) {
            float dot = 0.0f;
#pragma unroll
            for (int d = 0; d < FD; ++d) dot += u[oo * FD + d] * sv[oo * FD + d];
            float prev = first ? b_route[i * NCLS + oo] : bb_rd[base * NCLS + oo];
            nb[oo] = prev + dot;
        }
        if (o == 0) {
#pragma unroll
            for (int oo = 0; oo < NCLS; ++oo) bb_wr[base * NCLS + oo] = nb[oo];
        }
        float m = nb[0];
#pragma unroll
        for (int oo = 1; oo < NCLS; ++oo) m = fmaxf(m, nb[oo]);
        float s = 0.0f;
#pragma unroll
        for (int oo = 0; oo < NCLS; ++oo) s += expf(nb[oo] - m);
        float ci = expf(nb[o] - m) / s;
#pragma unroll
        for (int d = 0; d < FD; ++d) sd[d] += ci * u[o * FD + d];
    }
#pragma unroll
    for (int d = 0; d < FD; ++d)
        for (int off = 16; off; off >>= 1)
            sd[d] += __shfl_down_sync(0xffffffffu, sd[d], off);

    __shared__ float part[8][FD];
    __shared__ float fin[FD];
    __shared__ float fac;
    if (lane == 0)
#pragma unroll
        for (int d = 0; d < FD; ++d) part[wid][d] = sd[d];
    __syncthreads();
    if (t < FD) {
        float tot = 0.0f;
#pragma unroll
        for (int ww = 0; ww < 8; ++ww) tot += part[ww][t];
        fin[t] = tot;
    }
    __syncthreads();
    if (t == 0) {
        float l2 = 0.0f;
#pragma unroll
        for (int d = 0; d < FD; ++d) l2 += fin[d] * fin[d];
        fac = sqrtf(l2) / (1.0f + l2);
    }
    __syncthreads();
    if (t < FD) vout[((size_t)b * NCLS + o) * FD + t] = fin[t] * fac;
}

// =====================================================================
// heads
// =====================================================================
__global__ void head_kernel(const float* __restrict__ v,
                            const float* __restrict__ pred_w,
                            const float* __restrict__ pred_b,
                            const float* __restrict__ eos_w,
                            const float* __restrict__ eos_b,
                            float* __restrict__ out) {
    const int t = threadIdx.x;
    if (t >= BATCH * NCLS) return;
    const float* vv = v + (size_t)t * FD;
    float lg[NREL + 1];
#pragma unroll 4
    for (int r = 0; r < NREL; ++r) {
        float a = pred_b[r];
#pragma unroll
        for (int d = 0; d < FD; ++d) a += vv[d] * pred_w[r * FD + d];
        lg[r] = a;
    }
    {
        float a = eos_b[0];
#pragma unroll
        for (int d = 0; d < FD; ++d) a += vv[d] * eos_w[d];
        lg[NREL] = a;
    }
    float m = lg[0];
#pragma unroll
    for (int k = 1; k <= NREL; ++k) m = fmaxf(m, lg[k]);
    float s = 0.0f;
#pragma unroll
    for (int k = 0; k <= NREL; ++k) s += expf(lg[k] - m);
    const float ls = m + logf(s);
#pragma unroll
    for (int k = 0; k <= NREL; ++k) out[(size_t)t * (NREL + 1) + k] = lg[k] - ls;
}

// =====================================================================
extern "C" void kernel_launch(void* const* d_in, const int* in_sizes, int n_in,
                              void* d_out, int out_size) {
    const float* input   = (const float*)d_in[0];
    const float* conv1_w = (const float*)d_in[1];
    const float* conv1_b = (const float*)d_in[2];
    const float* prim_w  = (const float*)d_in[3];
    const float* prim_b  = (const float*)d_in[4];
    const float* caps_w  = (const float*)d_in[5];
    const float* b_route = (const float*)d_in[6];
    const float* pred_w  = (const float*)d_in[7];
    const float* pred_b  = (const float*)d_in[8];
    const float* eos_w   = (const float*)d_in[9];
    const float* eos_b   = (const float*)d_in[10];
    float* out = (float*)d_out;

    uint32_t* infp;
    uint4* w1fp;
    u16 *w2h, *c1;
    float *prim4, *upp, *bbp, *vp;
    cudaGetSymbolAddress((void**)&infp, g_inf);
    cudaGetSymbolAddress((void**)&w1fp, g_w1f);
    cudaGetSymbolAddress((void**)&w2h, g_w2h);
    cudaGetSymbolAddress((void**)&c1, g_c1);
    cudaGetSymbolAddress((void**)&prim4, g_prim4);
    cudaGetSymbolAddress((void**)&upp, g_up);
    cudaGetSymbolAddress((void**)&bbp, g_bb);
    cudaGetSymbolAddress((void**)&vp, g_v);

    const int NBB = BATCH * NCAP * NCLS;
    const int NV = BATCH * NCLS * FD;
    const size_t NINF = (size_t)BATCH * IH * 10 * 1024;

    prep_inf<<<(unsigned)((NINF + 255) / 256), 256>>>(input, infp);
    prep_c1wf<<<(300 * 16 * 32 * 4 + 255) / 256, 256>>>(conv1_w,
                                                        (uint32_t*)w1fp);
    prep_c2w<<<(256 * K2 + 255) / 256, 256>>>(prim_w, w2h);
    conv1_mma<<<dim3(2, OH1, BATCH), 256>>>(infp, w1fp, conv1_b, c1);
    conv2_mma<<<dim3(2, BATCH, KSPLIT), 256>>>(c1, w2h, prim_b, prim4);
    squash_predict_kernel<<<dim3(NCAP, BATCH), 80>>>(prim4, caps_w, upp);
    route_s0_kernel<<<dim3(NCLS, BATCH), 256>>>(upp, b_route, vp);
    route_fused<<<dim3(NCLS, BATCH), 256>>>(upp, b_route, vp, vp + NV,
                                            bbp, bbp, 1);
    route_fused<<<dim3(NCLS, BATCH), 256>>>(upp, b_route, vp + NV, vp,
                                            bbp, bbp + NBB, 0);
    route_fused<<<dim3(NCLS, BATCH), 256>>>(upp, b_route, vp, vp + NV,
                                            bbp + NBB, bbp, 0);
    head_kernel<<<1, BATCH * NCLS>>>(vp + NV, pred_w, pred_b, eos_w, eos_b, out);
}